// round 14
// baseline (speedup 1.0000x reference)
#include <cuda_runtime.h>
#include <cstdint>

#define NU 100000
#define NI 20000
#define NE 250000
#define H  128
#define HEADS 2
#define D  64

// ---------------- scratch (static device arrays; no allocation) ----------------
__device__ float g_zu [NU * H];
__device__ float g_zi [NI * H];
__device__ float g_zu2[NU * H];
__device__ float g_zi2[NI * H];
__device__ float g_xlu[NU * H];
__device__ float g_xru[NU * H];
__device__ float g_xli[NI * H];
__device__ float g_xri[NI * H];
__device__ float g_wtf[155648];     // tf32-rounded weights

// CSR (built once per call; graph identical across layers)
__device__ int g_rp_i [NI + 1];
__device__ int g_rp_u [NU + 1];
__device__ int g_cnt_i[NI];
__device__ int g_cnt_u[NU];
__device__ int g_col_i[NE];
__device__ int g_col_u[NE];
__device__ int g_bsum_i[32];
__device__ int g_bsum_u[32];

// ---------------- tf32 helpers -------------------------------------------------
__device__ __forceinline__ uint32_t f2tf32(float x) {
    uint32_t u;
    asm("cvt.rna.tf32.f32 %0, %1;" : "=r"(u) : "f"(x));
    return u;
}
__device__ __forceinline__ float rndtf32(float x) {
    return __uint_as_float(f2tf32(x));
}

#define WO_PU 0
#define WO_PI 8192
#define WO_WL 24576
#define WO_WR 90112
#define W_TOT 155648
__global__ void round_w(const float* __restrict__ pu, const float* __restrict__ pi,
                        const float* __restrict__ wl, const float* __restrict__ wr,
                        float* __restrict__ o) {
    int i = blockIdx.x * blockDim.x + threadIdx.x;
    float v;
    if (i < WO_PI) v = pu[i];
    else if (i < WO_WL) v = pi[i - WO_PI];
    else if (i < WO_WR) v = wl[i - WO_WL];
    else if (i < W_TOT) v = wr[i - WO_WR];
    else return;
    o[i] = rndtf32(v);
}

// ---------------- tf32 tensor-core GEMM, cp.async 2-stage pipeline -------------
#define BM 128
#define BN 128
#define BK 32
#define AST 36
#define BST 136
#define SMEM_BYTES ((2*BM*AST + 2*BK*BST) * 4)

template<int N> struct IC { static constexpr int v = N; };

__device__ __forceinline__ void cp16(uint32_t dst, const float* src, bool pred) {
    asm volatile("cp.async.ca.shared.global [%0], [%1], 16, %2;"
                 :: "r"(dst), "l"(src), "r"(pred ? 16 : 0));
}

template<int KTU, int KTI>
__global__ __launch_bounds__(256, 2) void gemm_fused(
    const float* __restrict__ Au, int Mu, int Ku,
    const float* __restrict__ Ai, int Mi, int Ki, int UB,
    const float* __restrict__ W00, const float* __restrict__ b00, float* __restrict__ C00,
    const float* __restrict__ W01, const float* __restrict__ b01, float* __restrict__ C01,
    const float* __restrict__ W10, const float* __restrict__ b10, float* __restrict__ C10,
    const float* __restrict__ W11, const float* __restrict__ b11, float* __restrict__ C11,
    int reluA, int cvtA, int roundC)
{
    extern __shared__ float smbuf[];
    const int sec = (blockIdx.y >= (unsigned)UB) ? 1 : 0;
    const float* A = sec ? Ai : Au;
    const int M = sec ? Mi : Mu;
    const int K = sec ? Ki : Ku;
    const int bm = (sec ? (blockIdx.y - UB) : blockIdx.y) * BM;

    const float* W; const float* bv; float* C;
    if (!sec) { if (blockIdx.x == 0) { W=W00; bv=b00; C=C00; } else { W=W01; bv=b01; C=C01; } }
    else      { if (blockIdx.x == 0) { W=W10; bv=b10; C=C10; } else { W=W11; bv=b11; C=C11; } }

    const int tid  = threadIdx.x;
    const int lane = tid & 31;
    const int warp = tid >> 5;
    const int wm   = warp >> 2;
    const int wn   = warp & 3;

    float* As = smbuf;
    float* Bs = smbuf + 2 * BM * AST;

    const int arow = tid >> 3;
    const int acol = (tid & 7) * 4;
    const int brow = tid >> 5;
    const int bcol = (tid & 31) * 4;

    float acc[4][4][4];
#pragma unroll
    for (int mt = 0; mt < 4; mt++)
#pragma unroll
        for (int nt = 0; nt < 4; nt++)
#pragma unroll
            for (int c = 0; c < 4; c++) acc[mt][nt][c] = 0.f;

    auto stage = [&](int kt, int buf) {
#pragma unroll
        for (int i = 0; i < 4; i++) {
            int row = arow + 32 * i;
            bool p = (bm + row) < M;
            int r = p ? (bm + row) : (M - 1);
            uint32_t d = (uint32_t)__cvta_generic_to_shared(As + buf * BM * AST + row * AST + acol);
            cp16(d, A + (size_t)r * K + kt * BK + acol, p);
        }
#pragma unroll
        for (int i = 0; i < 4; i++) {
            int kr = brow + 8 * i;
            uint32_t d = (uint32_t)__cvta_generic_to_shared(Bs + buf * BK * BST + kr * BST + bcol);
            cp16(d, W + (size_t)(kt * BK + kr) * BN + bcol, true);
        }
    };

    auto compute = [&](int buf) {
        const float* Asb = As + buf * BM * AST;
        const float* Bsb = Bs + buf * BK * BST;
#pragma unroll
        for (int kk = 0; kk < 4; kk++) {
            uint32_t a[4][4];
            {
                int row  = wm * 64 + (lane & 15);
                int koff = kk * 8 + ((lane >> 4) << 2);
#pragma unroll
                for (int mt = 0; mt < 4; mt++) {
                    uint32_t sa = (uint32_t)__cvta_generic_to_shared(
                        Asb + (row + mt * 16) * AST + koff);
                    asm volatile(
                        "ldmatrix.sync.aligned.m8n8.x4.shared.b16 {%0,%1,%2,%3}, [%4];"
                        : "=r"(a[mt][0]), "=r"(a[mt][1]), "=r"(a[mt][2]), "=r"(a[mt][3])
                        : "r"(sa));
                }
            }
            if (reluA) {
#pragma unroll
                for (int mt = 0; mt < 4; mt++)
#pragma unroll
                    for (int i = 0; i < 4; i++)
                        a[mt][i] = __float_as_uint(fmaxf(__uint_as_float(a[mt][i]), 0.f));
            }
            if (cvtA) {
#pragma unroll
                for (int mt = 0; mt < 4; mt++)
#pragma unroll
                    for (int i = 0; i < 4; i++)
                        a[mt][i] = f2tf32(__uint_as_float(a[mt][i]));
            }

            uint32_t b[4][2];
            {
                int kb = kk * 8 + (lane & 3);
                int nb = wn * 32 + (lane >> 2);
#pragma unroll
                for (int nt = 0; nt < 4; nt++) {
                    b[nt][0] = __float_as_uint(Bsb[kb * BST + nb + nt * 8]);
                    b[nt][1] = __float_as_uint(Bsb[(kb + 4) * BST + nb + nt * 8]);
                }
            }
#pragma unroll
            for (int mt = 0; mt < 4; mt++)
#pragma unroll
                for (int nt = 0; nt < 4; nt++) {
                    asm volatile(
                        "mma.sync.aligned.m16n8k8.row.col.f32.tf32.tf32.f32 "
                        "{%0,%1,%2,%3}, {%4,%5,%6,%7}, {%8,%9}, {%0,%1,%2,%3};"
                        : "+f"(acc[mt][nt][0]), "+f"(acc[mt][nt][1]),
                          "+f"(acc[mt][nt][2]), "+f"(acc[mt][nt][3])
                        : "r"(a[mt][0]), "r"(a[mt][1]), "r"(a[mt][2]), "r"(a[mt][3]),
                          "r"(b[nt][0]), "r"(b[nt][1]));
                }
        }
    };

    auto run = [&](auto ktc) {
        constexpr int KT = decltype(ktc)::v;
        stage(0, 0);
        asm volatile("cp.async.commit_group;");
#pragma unroll
        for (int kt = 0; kt < KT; kt++) {
            int buf = kt & 1;
            if (kt + 1 < KT) {
                stage(kt + 1, buf ^ 1);
                asm volatile("cp.async.commit_group;");
                asm volatile("cp.async.wait_group 1;");
            } else {
                asm volatile("cp.async.wait_group 0;");
            }
            __syncthreads();
            compute(buf);
            __syncthreads();
        }
    };
    if (sec == 0) run(IC<KTU>{});
    else          run(IC<KTI>{});

    const int r0 = bm + wm * 64 + (lane >> 2);
    const int cb = wn * 32 + 2 * (lane & 3);
#pragma unroll
    for (int mt = 0; mt < 4; mt++) {
#pragma unroll
        for (int nt = 0; nt < 4; nt++) {
            int row = r0 + mt * 16;
            int col = cb + nt * 8;
            float bx = bv[col], by = bv[col + 1];
            if (row < M) {
                float2 v = make_float2(acc[mt][nt][0] + bx, acc[mt][nt][1] + by);
                if (roundC) { v.x = rndtf32(v.x); v.y = rndtf32(v.y); }
                *(float2*)(C + (size_t)row * BN + col) = v;
            }
            if (row + 8 < M) {
                float2 v = make_float2(acc[mt][nt][2] + bx, acc[mt][nt][3] + by);
                if (roundC) { v.x = rndtf32(v.x); v.y = rndtf32(v.y); }
                *(float2*)(C + (size_t)(row + 8) * BN + col) = v;
            }
        }
    }
}

// ---------------- CSR construction (once per call) -----------------------------
__global__ void zero_counts(int* __restrict__ ci, int* __restrict__ cu) {
    int i = blockIdx.x * blockDim.x + threadIdx.x;
    if (i < NI) ci[i] = 0;
    if (i < NU) cu[i] = 0;
}

__global__ void build_hist(const int* __restrict__ es, const int* __restrict__ ed,
                           int* __restrict__ cu, int* __restrict__ ci, int nE) {
    int i = blockIdx.x * blockDim.x + threadIdx.x;
    if (i < nE) {
        atomicAdd(ci + ed[i], 1);
        atomicAdd(cu + es[i], 1);
    }
}

__global__ __launch_bounds__(1024) void scan_p1_both(
    const int* __restrict__ ci, int* __restrict__ bi, int nbi, int ni,
    const int* __restrict__ cu, int* __restrict__ bu, int nu)
{
    __shared__ int sh[1024];
    const int* cnt; int* bsums; int n; int blk;
    if ((int)blockIdx.x < nbi) { cnt = ci; bsums = bi; n = ni; blk = blockIdx.x; }
    else { cnt = cu; bsums = bu; n = nu; blk = blockIdx.x - nbi; }
    int base = blk * 4096;
    int t = threadIdx.x;
    int s = 0;
#pragma unroll
    for (int j = 0; j < 4; j++) {
        int i = base + t * 4 + j;
        if (i < n) s += cnt[i];
    }
    sh[t] = s;
    __syncthreads();
    for (int d = 512; d > 0; d >>= 1) {
        if (t < d) sh[t] += sh[t + d];
        __syncthreads();
    }
    if (t == 0) bsums[blk] = sh[0];
}

__global__ void scan_p2_both(int* __restrict__ bi, int nbi, int* __restrict__ rpi, int ni,
                             int* __restrict__ bu, int nbu, int* __restrict__ rpu, int nu) {
    int w = threadIdx.x >> 5;
    int t = threadIdx.x & 31;
    int* bs = w ? bu : bi;
    int nb = w ? nbu : nbi;
    int* rp = w ? rpu : rpi;
    int n  = w ? nu : ni;
    int own = (t < nb) ? bs[t] : 0;
    int v = own;
#pragma unroll
    for (int d = 1; d < 32; d <<= 1) {
        int u = __shfl_up_sync(0xffffffffu, v, d);
        if (t >= d) v += u;
    }
    if (t < nb) bs[t] = v - own;
    if (t == nb - 1) rp[n] = v;
}

__global__ __launch_bounds__(1024) void scan_p3_both(
    const int* __restrict__ ci, const int* __restrict__ bi, int nbi,
    int* __restrict__ rpi, int* __restrict__ curi, int ni,
    const int* __restrict__ cu, const int* __restrict__ bu,
    int* __restrict__ rpu, int* __restrict__ curu, int nu)
{
    __shared__ int sh[1024];
    const int* cnt; const int* bsums; int* rp; int* cur; int n; int blk;
    if ((int)blockIdx.x < nbi) { cnt = ci; bsums = bi; rp = rpi; cur = curi; n = ni; blk = blockIdx.x; }
    else { cnt = cu; bsums = bu; rp = rpu; cur = curu; n = nu; blk = blockIdx.x - nbi; }
    int base = blk * 4096;
    int t = threadIdx.x;
    int c[4];
    int s = 0;
#pragma unroll
    for (int j = 0; j < 4; j++) {
        int i = base + t * 4 + j;
        c[j] = (i < n) ? cnt[i] : 0;
        s += c[j];
    }
    sh[t] = s;
    __syncthreads();
    for (int d = 1; d < 1024; d <<= 1) {
        int v = (t >= d) ? sh[t - d] : 0;
        __syncthreads();
        sh[t] += v;
        __syncthreads();
    }
    int off = bsums[blk] + ((t > 0) ? sh[t - 1] : 0);
#pragma unroll
    for (int j = 0; j < 4; j++) {
        int i = base + t * 4 + j;
        if (i < n) {
            rp[i] = off;
            cur[i] = off;
            off += c[j];
        }
    }
}

__global__ void fill_csr(const int* __restrict__ es, const int* __restrict__ ed,
                         int* __restrict__ cur_u, int* __restrict__ cur_i,
                         int* __restrict__ col_u, int* __restrict__ col_i, int nE) {
    int i = blockIdx.x * blockDim.x + threadIdx.x;
    if (i < nE) {
        int s = es[i], t = ed[i];
        col_i[atomicAdd(cur_i + t, 1)] = s;
        col_u[atomicAdd(cur_u + s, 1)] = t;
    }
}

// ---------------- fused GATv2 gather (both relations of one layer) -------------
// Warp-cooperative index broadcast: one coalesced col[] load per 32-edge chunk,
// indices distributed via shfl -> per-edge critical path is just the xl gather.
__global__ __launch_bounds__(256) void gat_gather(
    const float* __restrict__ xlu, const float* __restrict__ xri,
    const float* __restrict__ att0, const float* __restrict__ bias0,
    float* __restrict__ outI,
    const float* __restrict__ xli, const float* __restrict__ xru,
    const float* __restrict__ att1, const float* __restrict__ bias1,
    float* __restrict__ outU,
    const int* __restrict__ rp_i, const int* __restrict__ col_i,
    const int* __restrict__ rp_u, const int* __restrict__ col_u,
    int roundOut)
{
    int w = (blockIdx.x * blockDim.x + threadIdx.x) >> 5;
    int lane = threadIdx.x & 31;

    const float* xl; const float* xr; const float* att; const float* bias;
    float* out; const int* rp; const int* col; int t;
    if (w < NI) {
        t = w; xl = xlu; xr = xri; att = att0; bias = bias0; out = outI;
        rp = rp_i; col = col_i;
    } else if (w < NI + NU) {
        t = w - NI; xl = xli; xr = xru; att = att1; bias = bias1; out = outU;
        rp = rp_u; col = col_u;
    } else return;

    int beg = rp[t], end = rp[t + 1];
    float4 b4 = *(const float4*)(bias + lane * 4);
    float* o = out + (size_t)t * H + lane * 4;

    if (beg == end) {
        if (roundOut) {
            b4.x = rndtf32(b4.x); b4.y = rndtf32(b4.y);
            b4.z = rndtf32(b4.z); b4.w = rndtf32(b4.w);
        }
        *(float4*)o = b4;
        return;
    }

    float4 xr4 = *(const float4*)(xr + (size_t)t * H + lane * 4);
    float4 at4 = *(const float4*)(att + lane * 4);

    float a0 = 0.f, a1 = 0.f, a2 = 0.f, a3 = 0.f, den = 0.f;
    const unsigned FULL = 0xffffffffu;

    for (int base = beg; base < end; base += 32) {
        int nIn = min(32, end - base);
        int sv = (base + lane < end) ? col[base + lane] : 0;

        int j = 0;
        for (; j + 2 <= nIn; j += 2) {
            int s0 = __shfl_sync(FULL, sv, j);
            int s1 = __shfl_sync(FULL, sv, j + 1);
            float4 xA = *(const float4*)(xl + (size_t)s0 * H + lane * 4);
            float4 xB = *(const float4*)(xl + (size_t)s1 * H + lane * 4);

            float eA0 = xA.x + xr4.x; eA0 = (eA0 > 0.f) ? eA0 : 0.2f * eA0;
            float eA1 = xA.y + xr4.y; eA1 = (eA1 > 0.f) ? eA1 : 0.2f * eA1;
            float eA2 = xA.z + xr4.z; eA2 = (eA2 > 0.f) ? eA2 : 0.2f * eA2;
            float eA3 = xA.w + xr4.w; eA3 = (eA3 > 0.f) ? eA3 : 0.2f * eA3;
            float pA = eA0 * at4.x + eA1 * at4.y + eA2 * at4.z + eA3 * at4.w;

            float eB0 = xB.x + xr4.x; eB0 = (eB0 > 0.f) ? eB0 : 0.2f * eB0;
            float eB1 = xB.y + xr4.y; eB1 = (eB1 > 0.f) ? eB1 : 0.2f * eB1;
            float eB2 = xB.z + xr4.z; eB2 = (eB2 > 0.f) ? eB2 : 0.2f * eB2;
            float eB3 = xB.w + xr4.w; eB3 = (eB3 > 0.f) ? eB3 : 0.2f * eB3;
            float pB = eB0 * at4.x + eB1 * at4.y + eB2 * at4.z + eB3 * at4.w;

#pragma unroll
            for (int off = 8; off > 0; off >>= 1) {
                pA += __shfl_xor_sync(FULL, pA, off);
                pB += __shfl_xor_sync(FULL, pB, off);
            }
            float peA = __expf(pA);
            float peB = __expf(pB);
            den += peA + peB;
            a0 += peA * xA.x + peB * xB.x;
            a1 += peA * xA.y + peB * xB.y;
            a2 += peA * xA.z + peB * xB.z;
            a3 += peA * xA.w + peB * xB.w;
        }
        if (j < nIn) {
            int s0 = __shfl_sync(FULL, sv, j);
            float4 xA = *(const float4*)(xl + (size_t)s0 * H + lane * 4);
            float eA0 = xA.x + xr4.x; eA0 = (eA0 > 0.f) ? eA0 : 0.2f * eA0;
            float eA1 = xA.y + xr4.y; eA1 = (eA1 > 0.f) ? eA1 : 0.2f * eA1;
            float eA2 = xA.z + xr4.z; eA2 = (eA2 > 0.f) ? eA2 : 0.2f * eA2;
            float eA3 = xA.w + xr4.w; eA3 = (eA3 > 0.f) ? eA3 : 0.2f * eA3;
            float pA = eA0 * at4.x + eA1 * at4.y + eA2 * at4.z + eA3 * at4.w;
#pragma unroll
            for (int off = 8; off > 0; off >>= 1)
                pA += __shfl_xor_sync(FULL, pA, off);
            float peA = __expf(pA);
            den += peA;
            a0 += peA * xA.x;
            a1 += peA * xA.y;
            a2 += peA * xA.z;
            a3 += peA * xA.w;
        }
    }

    float inv = 1.f / (den + 1e-16f);
    float4 r;
    r.x = a0 * inv + b4.x;
    r.y = a1 * inv + b4.y;
    r.z = a2 * inv + b4.z;
    r.w = a3 * inv + b4.w;
    if (roundOut) {
        r.x = rndtf32(r.x); r.y = rndtf32(r.y);
        r.z = rndtf32(r.z); r.w = rndtf32(r.w);
    }
    *(float4*)o = r;
}

extern "C" void kernel_launch(void* const* d_in, const int* in_sizes, int n_in,
                              void* d_out, int out_size)
{
    const float* x_user  = (const float*)d_in[0];
    const float* x_item  = (const float*)d_in[1];
    const float* Wp_user = (const float*)d_in[2];
    const float* bp_user = (const float*)d_in[3];
    const float* Wp_item = (const float*)d_in[4];
    const float* bp_item = (const float*)d_in[5];
    const float* Wl      = (const float*)d_in[6];
    const float* bl      = (const float*)d_in[7];
    const float* Wr      = (const float*)d_in[8];
    const float* br      = (const float*)d_in[9];
    const float* att     = (const float*)d_in[10];
    const float* bias    = (const float*)d_in[11];
    const int*   e_src   = (const int*)d_in[12];
    const int*   e_dst   = (const int*)d_in[13];
    const int    nE      = in_sizes[12];

    float* out = (float*)d_out;

    float *zu, *zi, *zu2, *zi2, *xlu, *xru, *xli, *xri, *wtf;
    int *rp_i, *rp_u, *cnt_i, *cnt_u, *col_i, *col_u, *bs_i, *bs_u;
    cudaGetSymbolAddress((void**)&zu,  g_zu);
    cudaGetSymbolAddress((void**)&zi,  g_zi);
    cudaGetSymbolAddress((void**)&zu2, g_zu2);
    cudaGetSymbolAddress((void**)&zi2, g_zi2);
    cudaGetSymbolAddress((void**)&xlu, g_xlu);
    cudaGetSymbolAddress((void**)&xru, g_xru);
    cudaGetSymbolAddress((void**)&xli, g_xli);
    cudaGetSymbolAddress((void**)&xri, g_xri);
    cudaGetSymbolAddress((void**)&wtf, g_wtf);
    cudaGetSymbolAddress((void**)&rp_i,  g_rp_i);
    cudaGetSymbolAddress((void**)&rp_u,  g_rp_u);
    cudaGetSymbolAddress((void**)&cnt_i, g_cnt_i);
    cudaGetSymbolAddress((void**)&cnt_u, g_cnt_u);
    cudaGetSymbolAddress((void**)&col_i, g_col_i);
    cudaGetSymbolAddress((void**)&col_u, g_col_u);
    cudaGetSymbolAddress((void**)&bs_i,  g_bsum_i);
    cudaGetSymbolAddress((void**)&bs_u,  g_bsum_u);

    cudaFuncSetAttribute(gemm_fused<2,4>, cudaFuncAttributeMaxDynamicSharedMemorySize, SMEM_BYTES);
    cudaFuncSetAttribute(gemm_fused<4,4>, cudaFuncAttributeMaxDynamicSharedMemorySize, SMEM_BYTES);

    // side stream + events (created once, before graph capture begins)
    static cudaStream_t s2 = nullptr;
    static cudaEvent_t evFork = nullptr, evJoin = nullptr;
    if (s2 == nullptr) {
        cudaStreamCreateWithFlags(&s2, cudaStreamNonBlocking);
        cudaEventCreateWithFlags(&evFork, cudaEventDisableTiming);
        cudaEventCreateWithFlags(&evJoin, cudaEventDisableTiming);
    }

    cudaStream_t st = 0;
    const int UB = (NU + BM - 1) / BM;
    const int IB = (NI + BM - 1) / BM;
    const int NB_I = (NI + 4095) / 4096;
    const int NB_U = (NU + 4095) / 4096;

    // ---- fork: CSR build on side stream, overlapped with weight-round + GEMMs ----
    cudaEventRecord(evFork, st);
    cudaStreamWaitEvent(s2, evFork, 0);

    zero_counts<<<(NU + 255) / 256, 256, 0, s2>>>(cnt_i, cnt_u);
    build_hist<<<(nE + 255) / 256, 256, 0, s2>>>(e_src, e_dst, cnt_u, cnt_i, nE);
    scan_p1_both<<<NB_I + NB_U, 1024, 0, s2>>>(cnt_i, bs_i, NB_I, NI, cnt_u, bs_u, NU);
    scan_p2_both<<<1, 64, 0, s2>>>(bs_i, NB_I, rp_i, NI, bs_u, NB_U, rp_u, NU);
    scan_p3_both<<<NB_I + NB_U, 1024, 0, s2>>>(cnt_i, bs_i, NB_I, rp_i, cnt_i, NI,
                                               cnt_u, bs_u, rp_u, cnt_u, NU);
    fill_csr<<<(nE + 255) / 256, 256, 0, s2>>>(e_src, e_dst, cnt_u, cnt_i, col_u, col_i, nE);
    cudaEventRecord(evJoin, s2);

    // ---- main stream: weights + projections ----
    round_w<<<(W_TOT + 255) / 256, 256, 0, st>>>(Wp_user, Wp_item, Wl, Wr, wtf);
    {
        dim3 grid(1, UB + IB);
        gemm_fused<2,4><<<grid, 256, SMEM_BYTES, st>>>(
            x_user, NU, 64, x_item, NI, 128, UB,
            wtf + WO_PU, bp_user, zu,  wtf + WO_PU, bp_user, zu,
            wtf + WO_PI, bp_item, zi,  wtf + WO_PI, bp_item, zi,
            0, 1, 1);
    }

    const int GBLK = ((NI + NU) * 32 + 255) / 256;
    bool joined = false;

    for (int l = 0; l < 2; l++) {
        const float* inU = (l == 0) ? zu : zu2;
        const float* inI = (l == 0) ? zi : zi2;
        float* outU = (l == 0) ? zu2 : out;
        float* outI = (l == 0) ? zi2 : out + (size_t)NU * H;

        int r0 = l * 2 + 0;
        int r1 = l * 2 + 1;

        {
            dim3 grid(2, UB + IB);
            gemm_fused<4,4><<<grid, 256, SMEM_BYTES, st>>>(
                inU, NU, H, inI, NI, H, UB,
                wtf + WO_WL + (size_t)r0 * 16384, bl + (size_t)r0 * H, xlu,
                wtf + WO_WR + (size_t)r1 * 16384, br + (size_t)r1 * H, xru,
                wtf + WO_WR + (size_t)r0 * 16384, br + (size_t)r0 * H, xri,
                wtf + WO_WL + (size_t)r1 * 16384, bl + (size_t)r1 * H, xli,
                (l == 1) ? 1 : 0, 0, 0);
        }

        if (!joined) {   // CSR must be ready before the first gather
            cudaStreamWaitEvent(st, evJoin, 0);
            joined = true;
        }

        gat_gather<<<GBLK, 256, 0, st>>>(
            xlu, xri, att + (size_t)r0 * H, bias + (size_t)r0 * H, outI,
            xli, xru, att + (size_t)r1 * H, bias + (size_t)r1 * H, outU,
            rp_i, col_i, rp_u, col_u,
            (l == 0) ? 1 : 0);
    }
}

// round 15
// speedup vs baseline: 1.1944x; 1.1944x over previous
#include <cuda_runtime.h>
#include <cstdint>

#define NU 100000
#define NI 20000
#define NE 250000
#define H  128
#define HEADS 2
#define D  64

// ---------------- scratch (static device arrays; no allocation) ----------------
__device__ float g_zu2[NU * H];
__device__ float g_zi2[NI * H];
__device__ float g_xlu[NU * H];
__device__ float g_xru[NU * H];
__device__ float g_xli[NI * H];
__device__ float g_xri[NI * H];
__device__ float g_wtf[155648];     // tf32-rounded weights (layer-1 linears used)
__device__ float g_wc [49664];      // composed layer-0 weights + biases

// CSR (built once per call; graph identical across layers)
__device__ int g_rp_i [NI + 1];
__device__ int g_rp_u [NU + 1];
__device__ int g_cnt_i[NI];
__device__ int g_cnt_u[NU];
__device__ int g_col_i[NE];
__device__ int g_col_u[NE];
__device__ int g_bsum_i[32];
__device__ int g_bsum_u[32];

// ---------------- tf32 helpers -------------------------------------------------
__device__ __forceinline__ uint32_t f2tf32(float x) {
    uint32_t u;
    asm("cvt.rna.tf32.f32 %0, %1;" : "=r"(u) : "f"(x));
    return u;
}
__device__ __forceinline__ float rndtf32(float x) {
    return __uint_as_float(f2tf32(x));
}

#define WO_PU 0
#define WO_PI 8192
#define WO_WL 24576
#define WO_WR 90112
#define W_TOT 155648
__global__ void round_w(const float* __restrict__ pu, const float* __restrict__ pi,
                        const float* __restrict__ wl, const float* __restrict__ wr,
                        float* __restrict__ o) {
    int i = blockIdx.x * blockDim.x + threadIdx.x;
    float v;
    if (i < WO_PI) v = pu[i];
    else if (i < WO_WL) v = pi[i - WO_PI];
    else if (i < WO_WR) v = wl[i - WO_WL];
    else if (i < W_TOT) v = wr[i - WO_WR];
    else return;
    o[i] = rndtf32(v);
}

// ---------------- layer-0 weight composition -----------------------------------
// W' = tf32( Wp[inDim,128] @ Ws[128,128] ),  b' = bp[128] @ Ws + bs[128].
// blockIdx.y selects one of 4 compositions; blockIdx.x = output row (inDim = bias row).
// g_wc layout: [u0 8192][u1 8192][i0 16384][i1 16384][b0..b3 4x128]
#define WC_U0 0
#define WC_U1 8192
#define WC_I0 16384
#define WC_I1 32768
#define WC_B  49152
__global__ __launch_bounds__(128) void compose_w(
    const float* __restrict__ Wp_u, const float* __restrict__ bp_u,
    const float* __restrict__ Wp_i, const float* __restrict__ bp_i,
    const float* __restrict__ Wl, const float* __restrict__ bl,
    const float* __restrict__ Wr, const float* __restrict__ br,
    float* __restrict__ wc)
{
    const size_t HH = (size_t)H * H;
    const float* Wp; const float* bp; const float* Ws; const float* bs;
    float* Wo; float* bo; int inDim;
    switch (blockIdx.y) {
        case 0:  Wp = Wp_u; bp = bp_u; Ws = Wl;      bs = bl;     Wo = wc + WC_U0; bo = wc + WC_B;       inDim = 64;  break; // xlu
        case 1:  Wp = Wp_u; bp = bp_u; Ws = Wr + HH; bs = br + H; Wo = wc + WC_U1; bo = wc + WC_B + 128; inDim = 64;  break; // xru
        case 2:  Wp = Wp_i; bp = bp_i; Ws = Wr;      bs = br;     Wo = wc + WC_I0; bo = wc + WC_B + 256; inDim = 128; break; // xri
        default: Wp = Wp_i; bp = bp_i; Ws = Wl + HH; bs = bl + H; Wo = wc + WC_I1; bo = wc + WC_B + 384; inDim = 128; break; // xli
    }
    int i = blockIdx.x;
    int j = threadIdx.x;
    if (i < inDim) {
        float s = 0.f;
#pragma unroll 8
        for (int k = 0; k < 128; k++)
            s += Wp[i * 128 + k] * Ws[k * 128 + j];
        Wo[i * 128 + j] = rndtf32(s);
    } else if (i == inDim) {
        float s = bs[j];
#pragma unroll 8
        for (int k = 0; k < 128; k++)
            s += bp[k] * Ws[k * 128 + j];
        bo[j] = s;
    }
}

// ---------------- tf32 tensor-core GEMM, cp.async 2-stage pipeline -------------
#define BM 128
#define BN 128
#define BK 32
#define AST 36
#define BST 136
#define SMEM_BYTES ((2*BM*AST + 2*BK*BST) * 4)

template<int N> struct IC { static constexpr int v = N; };

__device__ __forceinline__ void cp16(uint32_t dst, const float* src, bool pred) {
    asm volatile("cp.async.ca.shared.global [%0], [%1], 16, %2;"
                 :: "r"(dst), "l"(src), "r"(pred ? 16 : 0));
}

template<int KTU, int KTI>
__global__ __launch_bounds__(256, 2) void gemm_fused(
    const float* __restrict__ Au, int Mu, int Ku,
    const float* __restrict__ Ai, int Mi, int Ki, int UB,
    const float* __restrict__ W00, const float* __restrict__ b00, float* __restrict__ C00,
    const float* __restrict__ W01, const float* __restrict__ b01, float* __restrict__ C01,
    const float* __restrict__ W10, const float* __restrict__ b10, float* __restrict__ C10,
    const float* __restrict__ W11, const float* __restrict__ b11, float* __restrict__ C11,
    int reluA, int cvtA, int roundC)
{
    extern __shared__ float smbuf[];
    const int sec = (blockIdx.y >= (unsigned)UB) ? 1 : 0;
    const float* A = sec ? Ai : Au;
    const int M = sec ? Mi : Mu;
    const int K = sec ? Ki : Ku;
    const int bm = (sec ? (blockIdx.y - UB) : blockIdx.y) * BM;

    const float* W; const float* bv; float* C;
    if (!sec) { if (blockIdx.x == 0) { W=W00; bv=b00; C=C00; } else { W=W01; bv=b01; C=C01; } }
    else      { if (blockIdx.x == 0) { W=W10; bv=b10; C=C10; } else { W=W11; bv=b11; C=C11; } }

    const int tid  = threadIdx.x;
    const int lane = tid & 31;
    const int warp = tid >> 5;
    const int wm   = warp >> 2;
    const int wn   = warp & 3;

    float* As = smbuf;
    float* Bs = smbuf + 2 * BM * AST;

    const int arow = tid >> 3;
    const int acol = (tid & 7) * 4;
    const int brow = tid >> 5;
    const int bcol = (tid & 31) * 4;

    float acc[4][4][4];
#pragma unroll
    for (int mt = 0; mt < 4; mt++)
#pragma unroll
        for (int nt = 0; nt < 4; nt++)
#pragma unroll
            for (int c = 0; c < 4; c++) acc[mt][nt][c] = 0.f;

    auto stage = [&](int kt, int buf) {
#pragma unroll
        for (int i = 0; i < 4; i++) {
            int row = arow + 32 * i;
            bool p = (bm + row) < M;
            int r = p ? (bm + row) : (M - 1);
            uint32_t d = (uint32_t)__cvta_generic_to_shared(As + buf * BM * AST + row * AST + acol);
            cp16(d, A + (size_t)r * K + kt * BK + acol, p);
        }
#pragma unroll
        for (int i = 0; i < 4; i++) {
            int kr = brow + 8 * i;
            uint32_t d = (uint32_t)__cvta_generic_to_shared(Bs + buf * BK * BST + kr * BST + bcol);
            cp16(d, W + (size_t)(kt * BK + kr) * BN + bcol, true);
        }
    };

    auto compute = [&](int buf) {
        const float* Asb = As + buf * BM * AST;
        const float* Bsb = Bs + buf * BK * BST;
#pragma unroll
        for (int kk = 0; kk < 4; kk++) {
            uint32_t a[4][4];
            {
                int row  = wm * 64 + (lane & 15);
                int koff = kk * 8 + ((lane >> 4) << 2);
#pragma unroll
                for (int mt = 0; mt < 4; mt++) {
                    uint32_t sa = (uint32_t)__cvta_generic_to_shared(
                        Asb + (row + mt * 16) * AST + koff);
                    asm volatile(
                        "ldmatrix.sync.aligned.m8n8.x4.shared.b16 {%0,%1,%2,%3}, [%4];"
                        : "=r"(a[mt][0]), "=r"(a[mt][1]), "=r"(a[mt][2]), "=r"(a[mt][3])
                        : "r"(sa));
                }
            }
            if (reluA) {
#pragma unroll
                for (int mt = 0; mt < 4; mt++)
#pragma unroll
                    for (int i = 0; i < 4; i++)
                        a[mt][i] = __float_as_uint(fmaxf(__uint_as_float(a[mt][i]), 0.f));
            }
            if (cvtA) {
#pragma unroll
                for (int mt = 0; mt < 4; mt++)
#pragma unroll
                    for (int i = 0; i < 4; i++)
                        a[mt][i] = f2tf32(__uint_as_float(a[mt][i]));
            }

            uint32_t b[4][2];
            {
                int kb = kk * 8 + (lane & 3);
                int nb = wn * 32 + (lane >> 2);
#pragma unroll
                for (int nt = 0; nt < 4; nt++) {
                    b[nt][0] = __float_as_uint(Bsb[kb * BST + nb + nt * 8]);
                    b[nt][1] = __float_as_uint(Bsb[(kb + 4) * BST + nb + nt * 8]);
                }
            }
#pragma unroll
            for (int mt = 0; mt < 4; mt++)
#pragma unroll
                for (int nt = 0; nt < 4; nt++) {
                    asm volatile(
                        "mma.sync.aligned.m16n8k8.row.col.f32.tf32.tf32.f32 "
                        "{%0,%1,%2,%3}, {%4,%5,%6,%7}, {%8,%9}, {%0,%1,%2,%3};"
                        : "+f"(acc[mt][nt][0]), "+f"(acc[mt][nt][1]),
                          "+f"(acc[mt][nt][2]), "+f"(acc[mt][nt][3])
                        : "r"(a[mt][0]), "r"(a[mt][1]), "r"(a[mt][2]), "r"(a[mt][3]),
                          "r"(b[nt][0]), "r"(b[nt][1]));
                }
        }
    };

    auto run = [&](auto ktc) {
        constexpr int KT = decltype(ktc)::v;
        stage(0, 0);
        asm volatile("cp.async.commit_group;");
#pragma unroll
        for (int kt = 0; kt < KT; kt++) {
            int buf = kt & 1;
            if (kt + 1 < KT) {
                stage(kt + 1, buf ^ 1);
                asm volatile("cp.async.commit_group;");
                asm volatile("cp.async.wait_group 1;");
            } else {
                asm volatile("cp.async.wait_group 0;");
            }
            __syncthreads();
            compute(buf);
            __syncthreads();
        }
    };
    if (sec == 0) run(IC<KTU>{});
    else          run(IC<KTI>{});

    const int r0 = bm + wm * 64 + (lane >> 2);
    const int cb = wn * 32 + 2 * (lane & 3);
#pragma unroll
    for (int mt = 0; mt < 4; mt++) {
#pragma unroll
        for (int nt = 0; nt < 4; nt++) {
            int row = r0 + mt * 16;
            int col = cb + nt * 8;
            float bx = bv[col], by = bv[col + 1];
            if (row < M) {
                float2 v = make_float2(acc[mt][nt][0] + bx, acc[mt][nt][1] + by);
                if (roundC) { v.x = rndtf32(v.x); v.y = rndtf32(v.y); }
                *(float2*)(C + (size_t)row * BN + col) = v;
            }
            if (row + 8 < M) {
                float2 v = make_float2(acc[mt][nt][2] + bx, acc[mt][nt][3] + by);
                if (roundC) { v.x = rndtf32(v.x); v.y = rndtf32(v.y); }
                *(float2*)(C + (size_t)(row + 8) * BN + col) = v;
            }
        }
    }
}

// ---------------- CSR construction (once per call) -----------------------------
__global__ void zero_counts(int* __restrict__ ci, int* __restrict__ cu) {
    int i = blockIdx.x * blockDim.x + threadIdx.x;
    if (i < NI) ci[i] = 0;
    if (i < NU) cu[i] = 0;
}

__global__ void build_hist(const int* __restrict__ es, const int* __restrict__ ed,
                           int* __restrict__ cu, int* __restrict__ ci, int nE) {
    int i = blockIdx.x * blockDim.x + threadIdx.x;
    if (i < nE) {
        atomicAdd(ci + ed[i], 1);
        atomicAdd(cu + es[i], 1);
    }
}

__global__ __launch_bounds__(1024) void scan_p1_both(
    const int* __restrict__ ci, int* __restrict__ bi, int nbi, int ni,
    const int* __restrict__ cu, int* __restrict__ bu, int nu)
{
    __shared__ int sh[1024];
    const int* cnt; int* bsums; int n; int blk;
    if ((int)blockIdx.x < nbi) { cnt = ci; bsums = bi; n = ni; blk = blockIdx.x; }
    else { cnt = cu; bsums = bu; n = nu; blk = blockIdx.x - nbi; }
    int base = blk * 4096;
    int t = threadIdx.x;
    int s = 0;
#pragma unroll
    for (int j = 0; j < 4; j++) {
        int i = base + t * 4 + j;
        if (i < n) s += cnt[i];
    }
    sh[t] = s;
    __syncthreads();
    for (int d = 512; d > 0; d >>= 1) {
        if (t < d) sh[t] += sh[t + d];
        __syncthreads();
    }
    if (t == 0) bsums[blk] = sh[0];
}

__global__ void scan_p2_both(int* __restrict__ bi, int nbi, int* __restrict__ rpi, int ni,
                             int* __restrict__ bu, int nbu, int* __restrict__ rpu, int nu) {
    int w = threadIdx.x >> 5;
    int t = threadIdx.x & 31;
    int* bs = w ? bu : bi;
    int nb = w ? nbu : nbi;
    int* rp = w ? rpu : rpi;
    int n  = w ? nu : ni;
    int own = (t < nb) ? bs[t] : 0;
    int v = own;
#pragma unroll
    for (int d = 1; d < 32; d <<= 1) {
        int u = __shfl_up_sync(0xffffffffu, v, d);
        if (t >= d) v += u;
    }
    if (t < nb) bs[t] = v - own;
    if (t == nb - 1) rp[n] = v;
}

__global__ __launch_bounds__(1024) void scan_p3_both(
    const int* __restrict__ ci, const int* __restrict__ bi, int nbi,
    int* __restrict__ rpi, int* __restrict__ curi, int ni,
    const int* __restrict__ cu, const int* __restrict__ bu,
    int* __restrict__ rpu, int* __restrict__ curu, int nu)
{
    __shared__ int sh[1024];
    const int* cnt; const int* bsums; int* rp; int* cur; int n; int blk;
    if ((int)blockIdx.x < nbi) { cnt = ci; bsums = bi; rp = rpi; cur = curi; n = ni; blk = blockIdx.x; }
    else { cnt = cu; bsums = bu; rp = rpu; cur = curu; n = nu; blk = blockIdx.x - nbi; }
    int base = blk * 4096;
    int t = threadIdx.x;
    int c[4];
    int s = 0;
#pragma unroll
    for (int j = 0; j < 4; j++) {
        int i = base + t * 4 + j;
        c[j] = (i < n) ? cnt[i] : 0;
        s += c[j];
    }
    sh[t] = s;
    __syncthreads();
    for (int d = 1; d < 1024; d <<= 1) {
        int v = (t >= d) ? sh[t - d] : 0;
        __syncthreads();
        sh[t] += v;
        __syncthreads();
    }
    int off = bsums[blk] + ((t > 0) ? sh[t - 1] : 0);
#pragma unroll
    for (int j = 0; j < 4; j++) {
        int i = base + t * 4 + j;
        if (i < n) {
            rp[i] = off;
            cur[i] = off;
            off += c[j];
        }
    }
}

__global__ void fill_csr(const int* __restrict__ es, const int* __restrict__ ed,
                         int* __restrict__ cur_u, int* __restrict__ cur_i,
                         int* __restrict__ col_u, int* __restrict__ col_i, int nE) {
    int i = blockIdx.x * blockDim.x + threadIdx.x;
    if (i < nE) {
        int s = es[i], t = ed[i];
        col_i[atomicAdd(cur_i + t, 1)] = s;
        col_u[atomicAdd(cur_u + s, 1)] = t;
    }
}

// ---------------- fused GATv2 gather (both relations of one layer) -------------
// R8/R13 form — locked (all modifications regressed).
__global__ __launch_bounds__(256) void gat_gather(
    const float* __restrict__ xlu, const float* __restrict__ xri,
    const float* __restrict__ att0, const float* __restrict__ bias0,
    float* __restrict__ outI,
    const float* __restrict__ xli, const float* __restrict__ xru,
    const float* __restrict__ att1, const float* __restrict__ bias1,
    float* __restrict__ outU,
    const int* __restrict__ rp_i, const int* __restrict__ col_i,
    const int* __restrict__ rp_u, const int* __restrict__ col_u,
    int roundOut)
{
    int w = (blockIdx.x * blockDim.x + threadIdx.x) >> 5;
    int lane = threadIdx.x & 31;

    const float* xl; const float* xr; const float* att; const float* bias;
    float* out; const int* rp; const int* col; int t;
    if (w < NI) {
        t = w; xl = xlu; xr = xri; att = att0; bias = bias0; out = outI;
        rp = rp_i; col = col_i;
    } else if (w < NI + NU) {
        t = w - NI; xl = xli; xr = xru; att = att1; bias = bias1; out = outU;
        rp = rp_u; col = col_u;
    } else return;

    int beg = rp[t], end = rp[t + 1];
    float4 b4 = *(const float4*)(bias + lane * 4);
    float* o = out + (size_t)t * H + lane * 4;

    if (beg == end) {
        if (roundOut) {
            b4.x = rndtf32(b4.x); b4.y = rndtf32(b4.y);
            b4.z = rndtf32(b4.z); b4.w = rndtf32(b4.w);
        }
        *(float4*)o = b4;
        return;
    }

    float4 xr4 = *(const float4*)(xr + (size_t)t * H + lane * 4);
    float4 at4 = *(const float4*)(att + lane * 4);

    float a0 = 0.f, a1 = 0.f, a2 = 0.f, a3 = 0.f, den = 0.f;

    int e = beg;
    for (; e + 2 <= end; e += 2) {
        int s0 = col[e], s1 = col[e + 1];
        float4 xA = *(const float4*)(xl + (size_t)s0 * H + lane * 4);
        float4 xB = *(const float4*)(xl + (size_t)s1 * H + lane * 4);

        float eA0 = xA.x + xr4.x; eA0 = (eA0 > 0.f) ? eA0 : 0.2f * eA0;
        float eA1 = xA.y + xr4.y; eA1 = (eA1 > 0.f) ? eA1 : 0.2f * eA1;
        float eA2 = xA.z + xr4.z; eA2 = (eA2 > 0.f) ? eA2 : 0.2f * eA2;
        float eA3 = xA.w + xr4.w; eA3 = (eA3 > 0.f) ? eA3 : 0.2f * eA3;
        float pA = eA0 * at4.x + eA1 * at4.y + eA2 * at4.z + eA3 * at4.w;

        float eB0 = xB.x + xr4.x; eB0 = (eB0 > 0.f) ? eB0 : 0.2f * eB0;
        float eB1 = xB.y + xr4.y; eB1 = (eB1 > 0.f) ? eB1 : 0.2f * eB1;
        float eB2 = xB.z + xr4.z; eB2 = (eB2 > 0.f) ? eB2 : 0.2f * eB2;
        float eB3 = xB.w + xr4.w; eB3 = (eB3 > 0.f) ? eB3 : 0.2f * eB3;
        float pB = eB0 * at4.x + eB1 * at4.y + eB2 * at4.z + eB3 * at4.w;

#pragma unroll
        for (int off = 8; off > 0; off >>= 1) {
            pA += __shfl_xor_sync(0xffffffffu, pA, off);
            pB += __shfl_xor_sync(0xffffffffu, pB, off);
        }
        float peA = expf(pA);
        float peB = expf(pB);
        den += peA + peB;
        a0 += peA * xA.x + peB * xB.x;
        a1 += peA * xA.y + peB * xB.y;
        a2 += peA * xA.z + peB * xB.z;
        a3 += peA * xA.w + peB * xB.w;
    }
    if (e < end) {
        int s0 = col[e];
        float4 xA = *(const float4*)(xl + (size_t)s0 * H + lane * 4);
        float eA0 = xA.x + xr4.x; eA0 = (eA0 > 0.f) ? eA0 : 0.2f * eA0;
        float eA1 = xA.y + xr4.y; eA1 = (eA1 > 0.f) ? eA1 : 0.2f * eA1;
        float eA2 = xA.z + xr4.z; eA2 = (eA2 > 0.f) ? eA2 : 0.2f * eA2;
        float eA3 = xA.w + xr4.w; eA3 = (eA3 > 0.f) ? eA3 : 0.2f * eA3;
        float pA = eA0 * at4.x + eA1 * at4.y + eA2 * at4.z + eA3 * at4.w;
#pragma unroll
        for (int off = 8; off > 0; off >>= 1)
            pA += __shfl_xor_sync(0xffffffffu, pA, off);
        float peA = expf(pA);
        den += peA;
        a0 += peA * xA.x;
        a1 += peA * xA.y;
        a2 += peA * xA.z;
        a3 += peA * xA.w;
    }

    float inv = 1.f / (den + 1e-16f);
    float4 r;
    r.x = a0 * inv + b4.x;
    r.y = a1 * inv + b4.y;
    r.z = a2 * inv + b4.z;
    r.w = a3 * inv + b4.w;
    if (roundOut) {
        r.x = rndtf32(r.x); r.y = rndtf32(r.y);
        r.z = rndtf32(r.z); r.w = rndtf32(r.w);
    }
    *(float4*)o = r;
}

extern "C" void kernel_launch(void* const* d_in, const int* in_sizes, int n_in,
                              void* d_out, int out_size)
{
    const float* x_user  = (const float*)d_in[0];
    const float* x_item  = (const float*)d_in[1];
    const float* Wp_user = (const float*)d_in[2];
    const float* bp_user = (const float*)d_in[3];
    const float* Wp_item = (const float*)d_in[4];
    const float* bp_item = (const float*)d_in[5];
    const float* Wl      = (const float*)d_in[6];
    const float* bl      = (const float*)d_in[7];
    const float* Wr      = (const float*)d_in[8];
    const float* br      = (const float*)d_in[9];
    const float* att     = (const float*)d_in[10];
    const float* bias    = (const float*)d_in[11];
    const int*   e_src   = (const int*)d_in[12];
    const int*   e_dst   = (const int*)d_in[13];
    const int    nE      = in_sizes[12];

    float* out = (float*)d_out;

    float *zu2, *zi2, *xlu, *xru, *xli, *xri, *wtf, *wc;
    int *rp_i, *rp_u, *cnt_i, *cnt_u, *col_i, *col_u, *bs_i, *bs_u;
    cudaGetSymbolAddress((void**)&zu2, g_zu2);
    cudaGetSymbolAddress((void**)&zi2, g_zi2);
    cudaGetSymbolAddress((void**)&xlu, g_xlu);
    cudaGetSymbolAddress((void**)&xru, g_xru);
    cudaGetSymbolAddress((void**)&xli, g_xli);
    cudaGetSymbolAddress((void**)&xri, g_xri);
    cudaGetSymbolAddress((void**)&wtf, g_wtf);
    cudaGetSymbolAddress((void**)&wc,  g_wc);
    cudaGetSymbolAddress((void**)&rp_i,  g_rp_i);
    cudaGetSymbolAddress((void**)&rp_u,  g_rp_u);
    cudaGetSymbolAddress((void**)&cnt_i, g_cnt_i);
    cudaGetSymbolAddress((void**)&cnt_u, g_cnt_u);
    cudaGetSymbolAddress((void**)&col_i, g_col_i);
    cudaGetSymbolAddress((void**)&col_u, g_col_u);
    cudaGetSymbolAddress((void**)&bs_i,  g_bsum_i);
    cudaGetSymbolAddress((void**)&bs_u,  g_bsum_u);

    cudaFuncSetAttribute(gemm_fused<2,4>, cudaFuncAttributeMaxDynamicSharedMemorySize, SMEM_BYTES);
    cudaFuncSetAttribute(gemm_fused<4,4>, cudaFuncAttributeMaxDynamicSharedMemorySize, SMEM_BYTES);

    // side stream + events (created once, before graph capture begins)
    static cudaStream_t s2 = nullptr;
    static cudaEvent_t evFork = nullptr, evJoin = nullptr;
    if (s2 == nullptr) {
        cudaStreamCreateWithFlags(&s2, cudaStreamNonBlocking);
        cudaEventCreateWithFlags(&evFork, cudaEventDisableTiming);
        cudaEventCreateWithFlags(&evJoin, cudaEventDisableTiming);
    }

    cudaStream_t st = 0;
    const int UB = (NU + BM - 1) / BM;
    const int IB = (NI + BM - 1) / BM;
    const int NB_I = (NI + 4095) / 4096;
    const int NB_U = (NU + 4095) / 4096;

    // ---- fork: CSR build on side stream, overlapped with weight prep + GEMMs ----
    cudaEventRecord(evFork, st);
    cudaStreamWaitEvent(s2, evFork, 0);

    zero_counts<<<(NU + 255) / 256, 256, 0, s2>>>(cnt_i, cnt_u);
    build_hist<<<(nE + 255) / 256, 256, 0, s2>>>(e_src, e_dst, cnt_u, cnt_i, nE);
    scan_p1_both<<<NB_I + NB_U, 1024, 0, s2>>>(cnt_i, bs_i, NB_I, NI, cnt_u, bs_u, NU);
    scan_p2_both<<<1, 64, 0, s2>>>(bs_i, NB_I, rp_i, NI, bs_u, NB_U, rp_u, NU);
    scan_p3_both<<<NB_I + NB_U, 1024, 0, s2>>>(cnt_i, bs_i, NB_I, rp_i, cnt_i, NI,
                                               cnt_u, bs_u, rp_u, cnt_u, NU);
    fill_csr<<<(nE + 255) / 256, 256, 0, s2>>>(e_src, e_dst, cnt_u, cnt_i, col_u, col_i, nE);
    cudaEventRecord(evJoin, s2);

    // ---- main stream: weight prep (layer-1 rounding + layer-0 composition) ----
    round_w<<<(W_TOT + 255) / 256, 256, 0, st>>>(Wp_user, Wp_item, Wl, Wr, wtf);
    {
        dim3 grid(129, 4);   // 129 rows (128 + bias row) x 4 compositions
        compose_w<<<grid, 128, 0, st>>>(Wp_user, bp_user, Wp_item, bp_item,
                                        Wl, bl, Wr, br, wc);
    }

    const int GBLK = ((NI + NU) * 32 + 255) / 256;
    bool joined = false;

    for (int l = 0; l < 2; l++) {
        int r0 = l * 2 + 0;
        int r1 = l * 2 + 1;
        float* outU = (l == 0) ? zu2 : out;
        float* outI = (l == 0) ? zi2 : out + (size_t)NU * H;

        if (l == 0) {
            // fused projection+layer0: A = raw inputs, W = composed weights
            dim3 grid(2, UB + IB);
            gemm_fused<2,4><<<grid, 256, SMEM_BYTES, st>>>(
                x_user, NU, 64, x_item, NI, 128, UB,
                wc + WC_U0, wc + WC_B,       xlu,
                wc + WC_U1, wc + WC_B + 128, xru,
                wc + WC_I0, wc + WC_B + 256, xri,
                wc + WC_I1, wc + WC_B + 384, xli,
                0, 1, 0);
        } else {
            dim3 grid(2, UB + IB);
            gemm_fused<4,4><<<grid, 256, SMEM_BYTES, st>>>(
                zu2, NU, H, zi2, NI, H, UB,
                wtf + WO_WL + (size_t)r0 * 16384, bl + (size_t)r0 * H, xlu,
                wtf + WO_WR + (size_t)r1 * 16384, br + (size_t)r1 * H, xru,
                wtf + WO_WR + (size_t)r0 * 16384, br + (size_t)r0 * H, xri,
                wtf + WO_WL + (size_t)r1 * 16384, bl + (size_t)r1 * H, xli,
                1, 0, 0);
        }

        if (!joined) {   // CSR must be ready before the first gather
            cudaStreamWaitEvent(st, evJoin, 0);
            joined = true;
        }

        gat_gather<<<GBLK, 256, 0, st>>>(
            xlu, xri, att + (size_t)r0 * H, bias + (size_t)r0 * H, outI,
            xli, xru, att + (size_t)r1 * H, bias + (size_t)r1 * H, outU,
            rp_i, col_i, rp_u, col_u,
            (l == 0) ? 1 : 0);
    }
}

// round 16
// speedup vs baseline: 1.2012x; 1.0057x over previous
#include <cuda_runtime.h>
#include <cstdint>

#define NU 100000
#define NI 20000
#define NE 250000
#define H  128
#define HEADS 2
#define D  64

// ---------------- scratch (static device arrays; no allocation) ----------------
__device__ float g_zu2[NU * H];
__device__ float g_zi2[NI * H];
__device__ float g_xlu[NU * H];
__device__ float g_xru[NU * H];
__device__ float g_xli[NI * H];
__device__ float g_xri[NI * H];
__device__ float g_wtf[155648];     // tf32-rounded weights (layer-1 linears used)
__device__ float g_wc [49664];      // composed layer-0 weights + biases

// CSR (built once per call; graph identical across layers)
__device__ int g_rp_i [NI + 1];
__device__ int g_rp_u [NU + 1];
__device__ int g_cnt_i[NI];
__device__ int g_cnt_u[NU];
__device__ int g_col_i[NE];
__device__ int g_col_u[NE];
__device__ int g_bsum_i[32];
__device__ int g_bsum_u[32];

// ---------------- tf32 helpers -------------------------------------------------
__device__ __forceinline__ uint32_t f2tf32(float x) {
    uint32_t u;
    asm("cvt.rna.tf32.f32 %0, %1;" : "=r"(u) : "f"(x));
    return u;
}
__device__ __forceinline__ float rndtf32(float x) {
    return __uint_as_float(f2tf32(x));
}

#define WO_PU 0
#define WO_PI 8192
#define WO_WL 24576
#define WO_WR 90112
#define W_TOT 155648
__global__ void round_w(const float* __restrict__ pu, const float* __restrict__ pi,
                        const float* __restrict__ wl, const float* __restrict__ wr,
                        float* __restrict__ o) {
    int i = blockIdx.x * blockDim.x + threadIdx.x;
    float v;
    if (i < WO_PI) v = pu[i];
    else if (i < WO_WL) v = pi[i - WO_PI];
    else if (i < WO_WR) v = wl[i - WO_WL];
    else if (i < W_TOT) v = wr[i - WO_WR];
    else return;
    o[i] = rndtf32(v);
}

// ---------------- layer-0 weight composition -----------------------------------
#define WC_U0 0
#define WC_U1 8192
#define WC_I0 16384
#define WC_I1 32768
#define WC_B  49152
__global__ __launch_bounds__(128) void compose_w(
    const float* __restrict__ Wp_u, const float* __restrict__ bp_u,
    const float* __restrict__ Wp_i, const float* __restrict__ bp_i,
    const float* __restrict__ Wl, const float* __restrict__ bl,
    const float* __restrict__ Wr, const float* __restrict__ br,
    float* __restrict__ wc)
{
    const size_t HH = (size_t)H * H;
    const float* Wp; const float* bp; const float* Ws; const float* bs;
    float* Wo; float* bo; int inDim;
    switch (blockIdx.y) {
        case 0:  Wp = Wp_u; bp = bp_u; Ws = Wl;      bs = bl;     Wo = wc + WC_U0; bo = wc + WC_B;       inDim = 64;  break; // xlu
        case 1:  Wp = Wp_u; bp = bp_u; Ws = Wr + HH; bs = br + H; Wo = wc + WC_U1; bo = wc + WC_B + 128; inDim = 64;  break; // xru
        case 2:  Wp = Wp_i; bp = bp_i; Ws = Wr;      bs = br;     Wo = wc + WC_I0; bo = wc + WC_B + 256; inDim = 128; break; // xri
        default: Wp = Wp_i; bp = bp_i; Ws = Wl + HH; bs = bl + H; Wo = wc + WC_I1; bo = wc + WC_B + 384; inDim = 128; break; // xli
    }
    int i = blockIdx.x;
    int j = threadIdx.x;
    if (i < inDim) {
        float s = 0.f;
#pragma unroll 8
        for (int k = 0; k < 128; k++)
            s += Wp[i * 128 + k] * Ws[k * 128 + j];
        Wo[i * 128 + j] = rndtf32(s);
    } else if (i == inDim) {
        float s = bs[j];
#pragma unroll 8
        for (int k = 0; k < 128; k++)
            s += bp[k] * Ws[k * 128 + j];
        bo[j] = s;
    }
}

// ---------------- tf32 tensor-core GEMM, cp.async 2-stage pipeline -------------
#define BM 128
#define BN 128
#define BK 32
#define AST 36
#define BST 136
#define SMEM_BYTES ((2*BM*AST + 2*BK*BST) * 4)

template<int N> struct IC { static constexpr int v = N; };

__device__ __forceinline__ void cp16(uint32_t dst, const float* src, bool pred) {
    asm volatile("cp.async.ca.shared.global [%0], [%1], 16, %2;"
                 :: "r"(dst), "l"(src), "r"(pred ? 16 : 0));
}

template<int KTU, int KTI>
__global__ __launch_bounds__(256, 2) void gemm_fused(
    const float* __restrict__ Au, int Mu, int Ku,
    const float* __restrict__ Ai, int Mi, int Ki, int UB,
    const float* __restrict__ W00, const float* __restrict__ b00, float* __restrict__ C00,
    const float* __restrict__ W01, const float* __restrict__ b01, float* __restrict__ C01,
    const float* __restrict__ W10, const float* __restrict__ b10, float* __restrict__ C10,
    const float* __restrict__ W11, const float* __restrict__ b11, float* __restrict__ C11,
    int cvtA, int roundC)
{
    extern __shared__ float smbuf[];
    const int sec = (blockIdx.y >= (unsigned)UB) ? 1 : 0;
    const float* A = sec ? Ai : Au;
    const int M = sec ? Mi : Mu;
    const int K = sec ? Ki : Ku;
    const int bm = (sec ? (blockIdx.y - UB) : blockIdx.y) * BM;

    const float* W; const float* bv; float* C;
    if (!sec) { if (blockIdx.x == 0) { W=W00; bv=b00; C=C00; } else { W=W01; bv=b01; C=C01; } }
    else      { if (blockIdx.x == 0) { W=W10; bv=b10; C=C10; } else { W=W11; bv=b11; C=C11; } }

    const int tid  = threadIdx.x;
    const int lane = tid & 31;
    const int warp = tid >> 5;
    const int wm   = warp >> 2;
    const int wn   = warp & 3;

    float* As = smbuf;
    float* Bs = smbuf + 2 * BM * AST;

    const int arow = tid >> 3;
    const int acol = (tid & 7) * 4;
    const int brow = tid >> 5;
    const int bcol = (tid & 31) * 4;

    float acc[4][4][4];
#pragma unroll
    for (int mt = 0; mt < 4; mt++)
#pragma unroll
        for (int nt = 0; nt < 4; nt++)
#pragma unroll
            for (int c = 0; c < 4; c++) acc[mt][nt][c] = 0.f;

    auto stage = [&](int kt, int buf) {
#pragma unroll
        for (int i = 0; i < 4; i++) {
            int row = arow + 32 * i;
            bool p = (bm + row) < M;
            int r = p ? (bm + row) : (M - 1);
            uint32_t d = (uint32_t)__cvta_generic_to_shared(As + buf * BM * AST + row * AST + acol);
            cp16(d, A + (size_t)r * K + kt * BK + acol, p);
        }
#pragma unroll
        for (int i = 0; i < 4; i++) {
            int kr = brow + 8 * i;
            uint32_t d = (uint32_t)__cvta_generic_to_shared(Bs + buf * BK * BST + kr * BST + bcol);
            cp16(d, W + (size_t)(kt * BK + kr) * BN + bcol, true);
        }
    };

    auto compute = [&](int buf) {
        const float* Asb = As + buf * BM * AST;
        const float* Bsb = Bs + buf * BK * BST;
#pragma unroll
        for (int kk = 0; kk < 4; kk++) {
            uint32_t a[4][4];
            {
                int row  = wm * 64 + (lane & 15);
                int koff = kk * 8 + ((lane >> 4) << 2);
#pragma unroll
                for (int mt = 0; mt < 4; mt++) {
                    uint32_t sa = (uint32_t)__cvta_generic_to_shared(
                        Asb + (row + mt * 16) * AST + koff);
                    asm volatile(
                        "ldmatrix.sync.aligned.m8n8.x4.shared.b16 {%0,%1,%2,%3}, [%4];"
                        : "=r"(a[mt][0]), "=r"(a[mt][1]), "=r"(a[mt][2]), "=r"(a[mt][3])
                        : "r"(sa));
                }
            }
            if (cvtA) {
#pragma unroll
                for (int mt = 0; mt < 4; mt++)
#pragma unroll
                    for (int i = 0; i < 4; i++)
                        a[mt][i] = f2tf32(__uint_as_float(a[mt][i]));
            }

            uint32_t b[4][2];
            {
                int kb = kk * 8 + (lane & 3);
                int nb = wn * 32 + (lane >> 2);
#pragma unroll
                for (int nt = 0; nt < 4; nt++) {
                    b[nt][0] = __float_as_uint(Bsb[kb * BST + nb + nt * 8]);
                    b[nt][1] = __float_as_uint(Bsb[(kb + 4) * BST + nb + nt * 8]);
                }
            }
#pragma unroll
            for (int mt = 0; mt < 4; mt++)
#pragma unroll
                for (int nt = 0; nt < 4; nt++) {
                    asm volatile(
                        "mma.sync.aligned.m16n8k8.row.col.f32.tf32.tf32.f32 "
                        "{%0,%1,%2,%3}, {%4,%5,%6,%7}, {%8,%9}, {%0,%1,%2,%3};"
                        : "+f"(acc[mt][nt][0]), "+f"(acc[mt][nt][1]),
                          "+f"(acc[mt][nt][2]), "+f"(acc[mt][nt][3])
                        : "r"(a[mt][0]), "r"(a[mt][1]), "r"(a[mt][2]), "r"(a[mt][3]),
                          "r"(b[nt][0]), "r"(b[nt][1]));
                }
        }
    };

    auto run = [&](auto ktc) {
        constexpr int KT = decltype(ktc)::v;
        stage(0, 0);
        asm volatile("cp.async.commit_group;");
#pragma unroll
        for (int kt = 0; kt < KT; kt++) {
            int buf = kt & 1;
            if (kt + 1 < KT) {
                stage(kt + 1, buf ^ 1);
                asm volatile("cp.async.commit_group;");
                asm volatile("cp.async.wait_group 1;");
            } else {
                asm volatile("cp.async.wait_group 0;");
            }
            __syncthreads();
            compute(buf);
            __syncthreads();
        }
    };
    if (sec == 0) run(IC<KTU>{});
    else          run(IC<KTI>{});

    const int r0 = bm + wm * 64 + (lane >> 2);
    const int cb = wn * 32 + 2 * (lane & 3);
#pragma unroll
    for (int mt = 0; mt < 4; mt++) {
#pragma unroll
        for (int nt = 0; nt < 4; nt++) {
            int row = r0 + mt * 16;
            int col = cb + nt * 8;
            float bx = bv[col], by = bv[col + 1];
            if (row < M) {
                float2 v = make_float2(acc[mt][nt][0] + bx, acc[mt][nt][1] + by);
                if (roundC) { v.x = rndtf32(v.x); v.y = rndtf32(v.y); }
                *(float2*)(C + (size_t)row * BN + col) = v;
            }
            if (row + 8 < M) {
                float2 v = make_float2(acc[mt][nt][2] + bx, acc[mt][nt][3] + by);
                if (roundC) { v.x = rndtf32(v.x); v.y = rndtf32(v.y); }
                *(float2*)(C + (size_t)(row + 8) * BN + col) = v;
            }
        }
    }
}

// ---------------- CSR construction (once per call) -----------------------------
__global__ void zero_counts(int* __restrict__ ci, int* __restrict__ cu) {
    int i = blockIdx.x * blockDim.x + threadIdx.x;
    if (i < NI) ci[i] = 0;
    if (i < NU) cu[i] = 0;
}

__global__ void build_hist(const int* __restrict__ es, const int* __restrict__ ed,
                           int* __restrict__ cu, int* __restrict__ ci, int nE) {
    int i = blockIdx.x * blockDim.x + threadIdx.x;
    if (i < nE) {
        atomicAdd(ci + ed[i], 1);
        atomicAdd(cu + es[i], 1);
    }
}

__global__ __launch_bounds__(1024) void scan_p1_both(
    const int* __restrict__ ci, int* __restrict__ bi, int nbi, int ni,
    const int* __restrict__ cu, int* __restrict__ bu, int nu)
{
    __shared__ int sh[1024];
    const int* cnt; int* bsums; int n; int blk;
    if ((int)blockIdx.x < nbi) { cnt = ci; bsums = bi; n = ni; blk = blockIdx.x; }
    else { cnt = cu; bsums = bu; n = nu; blk = blockIdx.x - nbi; }
    int base = blk * 4096;
    int t = threadIdx.x;
    int s = 0;
#pragma unroll
    for (int j = 0; j < 4; j++) {
        int i = base + t * 4 + j;
        if (i < n) s += cnt[i];
    }
    sh[t] = s;
    __syncthreads();
    for (int d = 512; d > 0; d >>= 1) {
        if (t < d) sh[t] += sh[t + d];
        __syncthreads();
    }
    if (t == 0) bsums[blk] = sh[0];
}

__global__ void scan_p2_both(int* __restrict__ bi, int nbi, int* __restrict__ rpi, int ni,
                             int* __restrict__ bu, int nbu, int* __restrict__ rpu, int nu) {
    int w = threadIdx.x >> 5;
    int t = threadIdx.x & 31;
    int* bs = w ? bu : bi;
    int nb = w ? nbu : nbi;
    int* rp = w ? rpu : rpi;
    int n  = w ? nu : ni;
    int own = (t < nb) ? bs[t] : 0;
    int v = own;
#pragma unroll
    for (int d = 1; d < 32; d <<= 1) {
        int u = __shfl_up_sync(0xffffffffu, v, d);
        if (t >= d) v += u;
    }
    if (t < nb) bs[t] = v - own;
    if (t == nb - 1) rp[n] = v;
}

__global__ __launch_bounds__(1024) void scan_p3_both(
    const int* __restrict__ ci, const int* __restrict__ bi, int nbi,
    int* __restrict__ rpi, int* __restrict__ curi, int ni,
    const int* __restrict__ cu, const int* __restrict__ bu,
    int* __restrict__ rpu, int* __restrict__ curu, int nu)
{
    __shared__ int sh[1024];
    const int* cnt; const int* bsums; int* rp; int* cur; int n; int blk;
    if ((int)blockIdx.x < nbi) { cnt = ci; bsums = bi; rp = rpi; cur = curi; n = ni; blk = blockIdx.x; }
    else { cnt = cu; bsums = bu; rp = rpu; cur = curu; n = nu; blk = blockIdx.x - nbi; }
    int base = blk * 4096;
    int t = threadIdx.x;
    int c[4];
    int s = 0;
#pragma unroll
    for (int j = 0; j < 4; j++) {
        int i = base + t * 4 + j;
        c[j] = (i < n) ? cnt[i] : 0;
        s += c[j];
    }
    sh[t] = s;
    __syncthreads();
    for (int d = 1; d < 1024; d <<= 1) {
        int v = (t >= d) ? sh[t - d] : 0;
        __syncthreads();
        sh[t] += v;
        __syncthreads();
    }
    int off = bsums[blk] + ((t > 0) ? sh[t - 1] : 0);
#pragma unroll
    for (int j = 0; j < 4; j++) {
        int i = base + t * 4 + j;
        if (i < n) {
            rp[i] = off;
            cur[i] = off;
            off += c[j];
        }
    }
}

__global__ void fill_csr(const int* __restrict__ es, const int* __restrict__ ed,
                         int* __restrict__ cur_u, int* __restrict__ cur_i,
                         int* __restrict__ col_u, int* __restrict__ col_i, int nE) {
    int i = blockIdx.x * blockDim.x + threadIdx.x;
    if (i < nE) {
        int s = es[i], t = ed[i];
        col_i[atomicAdd(cur_i + t, 1)] = s;
        col_u[atomicAdd(cur_u + s, 1)] = t;
    }
}

// ---------------- fused GATv2 gather (both relations of one layer) -------------
// R8/R13 loop form — locked. postOut=1: apply relu then tf32-round at write
// (feeds layer-1 GEMM A); postOut=0: plain write (final output).
__global__ __launch_bounds__(256) void gat_gather(
    const float* __restrict__ xlu, const float* __restrict__ xri,
    const float* __restrict__ att0, const float* __restrict__ bias0,
    float* __restrict__ outI,
    const float* __restrict__ xli, const float* __restrict__ xru,
    const float* __restrict__ att1, const float* __restrict__ bias1,
    float* __restrict__ outU,
    const int* __restrict__ rp_i, const int* __restrict__ col_i,
    const int* __restrict__ rp_u, const int* __restrict__ col_u,
    int postOut)
{
    int w = (blockIdx.x * blockDim.x + threadIdx.x) >> 5;
    int lane = threadIdx.x & 31;

    const float* xl; const float* xr; const float* att; const float* bias;
    float* out; const int* rp; const int* col; int t;
    if (w < NI) {
        t = w; xl = xlu; xr = xri; att = att0; bias = bias0; out = outI;
        rp = rp_i; col = col_i;
    } else if (w < NI + NU) {
        t = w - NI; xl = xli; xr = xru; att = att1; bias = bias1; out = outU;
        rp = rp_u; col = col_u;
    } else return;

    int beg = rp[t], end = rp[t + 1];
    float4 b4 = *(const float4*)(bias + lane * 4);
    float* o = out + (size_t)t * H + lane * 4;

    if (beg == end) {
        if (postOut) {
            b4.x = rndtf32(fmaxf(b4.x, 0.f)); b4.y = rndtf32(fmaxf(b4.y, 0.f));
            b4.z = rndtf32(fmaxf(b4.z, 0.f)); b4.w = rndtf32(fmaxf(b4.w, 0.f));
        }
        *(float4*)o = b4;
        return;
    }

    float4 xr4 = *(const float4*)(xr + (size_t)t * H + lane * 4);
    float4 at4 = *(const float4*)(att + lane * 4);

    float a0 = 0.f, a1 = 0.f, a2 = 0.f, a3 = 0.f, den = 0.f;

    int e = beg;
    for (; e + 2 <= end; e += 2) {
        int s0 = col[e], s1 = col[e + 1];
        float4 xA = *(const float4*)(xl + (size_t)s0 * H + lane * 4);
        float4 xB = *(const float4*)(xl + (size_t)s1 * H + lane * 4);

        float eA0 = xA.x + xr4.x; eA0 = (eA0 > 0.f) ? eA0 : 0.2f * eA0;
        float eA1 = xA.y + xr4.y; eA1 = (eA1 > 0.f) ? eA1 : 0.2f * eA1;
        float eA2 = xA.z + xr4.z; eA2 = (eA2 > 0.f) ? eA2 : 0.2f * eA2;
        float eA3 = xA.w + xr4.w; eA3 = (eA3 > 0.f) ? eA3 : 0.2f * eA3;
        float pA = eA0 * at4.x + eA1 * at4.y + eA2 * at4.z + eA3 * at4.w;

        float eB0 = xB.x + xr4.x; eB0 = (eB0 > 0.f) ? eB0 : 0.2f * eB0;
        float eB1 = xB.y + xr4.y; eB1 = (eB1 > 0.f) ? eB1 : 0.2f * eB1;
        float eB2 = xB.z + xr4.z; eB2 = (eB2 > 0.f) ? eB2 : 0.2f * eB2;
        float eB3 = xB.w + xr4.w; eB3 = (eB3 > 0.f) ? eB3 : 0.2f * eB3;
        float pB = eB0 * at4.x + eB1 * at4.y + eB2 * at4.z + eB3 * at4.w;

#pragma unroll
        for (int off = 8; off > 0; off >>= 1) {
            pA += __shfl_xor_sync(0xffffffffu, pA, off);
            pB += __shfl_xor_sync(0xffffffffu, pB, off);
        }
        float peA = expf(pA);
        float peB = expf(pB);
        den += peA + peB;
        a0 += peA * xA.x + peB * xB.x;
        a1 += peA * xA.y + peB * xB.y;
        a2 += peA * xA.z + peB * xB.z;
        a3 += peA * xA.w + peB * xB.w;
    }
    if (e < end) {
        int s0 = col[e];
        float4 xA = *(const float4*)(xl + (size_t)s0 * H + lane * 4);
        float eA0 = xA.x + xr4.x; eA0 = (eA0 > 0.f) ? eA0 : 0.2f * eA0;
        float eA1 = xA.y + xr4.y; eA1 = (eA1 > 0.f) ? eA1 : 0.2f * eA1;
        float eA2 = xA.z + xr4.z; eA2 = (eA2 > 0.f) ? eA2 : 0.2f * eA2;
        float eA3 = xA.w + xr4.w; eA3 = (eA3 > 0.f) ? eA3 : 0.2f * eA3;
        float pA = eA0 * at4.x + eA1 * at4.y + eA2 * at4.z + eA3 * at4.w;
#pragma unroll
        for (int off = 8; off > 0; off >>= 1)
            pA += __shfl_xor_sync(0xffffffffu, pA, off);
        float peA = expf(pA);
        den += peA;
        a0 += peA * xA.x;
        a1 += peA * xA.y;
        a2 += peA * xA.z;
        a3 += peA * xA.w;
    }

    float inv = 1.f / (den + 1e-16f);
    float4 r;
    r.x = a0 * inv + b4.x;
    r.y = a1 * inv + b4.y;
    r.z = a2 * inv + b4.z;
    r.w = a3 * inv + b4.w;
    if (postOut) {
        r.x = rndtf32(fmaxf(r.x, 0.f)); r.y = rndtf32(fmaxf(r.y, 0.f));
        r.z = rndtf32(fmaxf(r.z, 0.f)); r.w = rndtf32(fmaxf(r.w, 0.f));
    }
    *(float4*)o = r;
}

extern "C" void kernel_launch(void* const* d_in, const int* in_sizes, int n_in,
                              void* d_out, int out_size)
{
    const float* x_user  = (const float*)d_in[0];
    const float* x_item  = (const float*)d_in[1];
    const float* Wp_user = (const float*)d_in[2];
    const float* bp_user = (const float*)d_in[3];
    const float* Wp_item = (const float*)d_in[4];
    const float* bp_item = (const float*)d_in[5];
    const float* Wl      = (const float*)d_in[6];
    const float* bl      = (const float*)d_in[7];
    const float* Wr      = (const float*)d_in[8];
    const float* br      = (const float*)d_in[9];
    const float* att     = (const float*)d_in[10];
    const float* bias    = (const float*)d_in[11];
    const int*   e_src   = (const int*)d_in[12];
    const int*   e_dst   = (const int*)d_in[13];
    const int    nE      = in_sizes[12];

    float* out = (float*)d_out;

    float *zu2, *zi2, *xlu, *xru, *xli, *xri, *wtf, *wc;
    int *rp_i, *rp_u, *cnt_i, *cnt_u, *col_i, *col_u, *bs_i, *bs_u;
    cudaGetSymbolAddress((void**)&zu2, g_zu2);
    cudaGetSymbolAddress((void**)&zi2, g_zi2);
    cudaGetSymbolAddress((void**)&xlu, g_xlu);
    cudaGetSymbolAddress((void**)&xru, g_xru);
    cudaGetSymbolAddress((void**)&xli, g_xli);
    cudaGetSymbolAddress((void**)&xri, g_xri);
    cudaGetSymbolAddress((void**)&wtf, g_wtf);
    cudaGetSymbolAddress((void**)&wc,  g_wc);
    cudaGetSymbolAddress((void**)&rp_i,  g_rp_i);
    cudaGetSymbolAddress((void**)&rp_u,  g_rp_u);
    cudaGetSymbolAddress((void**)&cnt_i, g_cnt_i);
    cudaGetSymbolAddress((void**)&cnt_u, g_cnt_u);
    cudaGetSymbolAddress((void**)&col_i, g_col_i);
    cudaGetSymbolAddress((void**)&col_u, g_col_u);
    cudaGetSymbolAddress((void**)&bs_i,  g_bsum_i);
    cudaGetSymbolAddress((void**)&bs_u,  g_bsum_u);

    cudaFuncSetAttribute(gemm_fused<2,4>, cudaFuncAttributeMaxDynamicSharedMemorySize, SMEM_BYTES);
    cudaFuncSetAttribute(gemm_fused<4,4>, cudaFuncAttributeMaxDynamicSharedMemorySize, SMEM_BYTES);

    // side stream + events (created once, before graph capture begins)
    static cudaStream_t s2 = nullptr;
    static cudaEvent_t evFork = nullptr, evJoin = nullptr;
    if (s2 == nullptr) {
        cudaStreamCreateWithFlags(&s2, cudaStreamNonBlocking);
        cudaEventCreateWithFlags(&evFork, cudaEventDisableTiming);
        cudaEventCreateWithFlags(&evJoin, cudaEventDisableTiming);
    }

    cudaStream_t st = 0;
    const int UB = (NU + BM - 1) / BM;
    const int IB = (NI + BM - 1) / BM;
    const int NB_I = (NI + 4095) / 4096;
    const int NB_U = (NU + 4095) / 4096;

    // ---- fork: CSR build + layer-1 weight rounding on side stream ----
    // (wtf consumed only by the L1 GEMM, which is ordered after the main
    //  stream's evJoin wait -> safe)
    cudaEventRecord(evFork, st);
    cudaStreamWaitEvent(s2, evFork, 0);

    zero_counts<<<(NU + 255) / 256, 256, 0, s2>>>(cnt_i, cnt_u);
    build_hist<<<(nE + 255) / 256, 256, 0, s2>>>(e_src, e_dst, cnt_u, cnt_i, nE);
    scan_p1_both<<<NB_I + NB_U, 1024, 0, s2>>>(cnt_i, bs_i, NB_I, NI, cnt_u, bs_u, NU);
    scan_p2_both<<<1, 64, 0, s2>>>(bs_i, NB_I, rp_i, NI, bs_u, NB_U, rp_u, NU);
    scan_p3_both<<<NB_I + NB_U, 1024, 0, s2>>>(cnt_i, bs_i, NB_I, rp_i, cnt_i, NI,
                                               cnt_u, bs_u, rp_u, cnt_u, NU);
    fill_csr<<<(nE + 255) / 256, 256, 0, s2>>>(e_src, e_dst, cnt_u, cnt_i, col_u, col_i, nE);
    round_w<<<(W_TOT + 255) / 256, 256, 0, s2>>>(Wp_user, Wp_item, Wl, Wr, wtf);
    cudaEventRecord(evJoin, s2);

    // ---- main stream: layer-0 weight composition (critical-path head) ----
    {
        dim3 grid(129, 4);
        compose_w<<<grid, 128, 0, st>>>(Wp_user, bp_user, Wp_item, bp_item,
                                        Wl, bl, Wr, br, wc);
    }

    const int GBLK = ((NI + NU) * 32 + 255) / 256;
    bool joined = false;

    for (int l = 0; l < 2; l++) {
        int r0 = l * 2 + 0;
        int r1 = l * 2 + 1;
        float* outU = (l == 0) ? zu2 : out;
        float* outI = (l == 0) ? zi2 : out + (size_t)NU * H;

        if (l == 0) {
            // fused projection+layer0: A = raw inputs, W = composed weights
            dim3 grid(2, UB + IB);
            gemm_fused<2,4><<<grid, 256, SMEM_BYTES, st>>>(
                x_user, NU, 64, x_item, NI, 128, UB,
                wc + WC_U0, wc + WC_B,       xlu,
                wc + WC_U1, wc + WC_B + 128, xru,
                wc + WC_I0, wc + WC_B + 256, xri,
                wc + WC_I1, wc + WC_B + 384, xli,
                1, 0);
        } else {
            // layer 1: A (zu2/zi2) already relu'd + tf32-rounded by gather-0
            dim3 grid(2, UB + IB);
            gemm_fused<4,4><<<grid, 256, SMEM_BYTES, st>>>(
                zu2, NU, H, zi2, NI, H, UB,
                wtf + WO_WL + (size_t)r0 * 16384, bl + (size_t)r0 * H, xlu,
                wtf + WO_WR + (size_t)r1 * 16384, br + (size_t)r1 * H, xru,
                wtf + WO_WR + (size_t)r0 * 16384, br + (size_t)r0 * H, xri,
                wtf + WO_WL + (size_t)r1 * 16384, bl + (size_t)r1 * H, xli,
                0, 0);
        }

        if (!joined) {   // CSR (and wtf) must be ready before the first gather
            cudaStreamWaitEvent(st, evJoin, 0);
            joined = true;
        }

        gat_gather<<<GBLK, 256, 0, st>>>(
            xlu, xri, att + (size_t)r0 * H, bias + (size_t)r0 * H, outI,
            xli, xru, att + (size_t)r1 * H, bias + (size_t)r1 * H, outU,
            rp_i, col_i, rp_u, col_u,
            (l == 0) ? 1 : 0);
    }
}

// round 17
// speedup vs baseline: 1.2031x; 1.0015x over previous
#include <cuda_runtime.h>
#include <cstdint>

#define NU 100000
#define NI 20000
#define NE 250000
#define H  128
#define HEADS 2
#define D  64

// ---------------- scratch (static device arrays; no allocation) ----------------
__device__ float g_zu2[NU * H];
__device__ float g_zi2[NI * H];
__device__ float g_xlu[NU * H];
__device__ float g_xru[NU * H];
__device__ float g_xli[NI * H];
__device__ float g_xri[NI * H];
__device__ float g_wtf[155648];     // tf32-rounded weights (layer-1 linears used)
__device__ float g_wc [49664];      // composed layer-0 weights + biases

// CSR (built once per call; graph identical across layers)
__device__ int g_rp_i [NI + 1];
__device__ int g_rp_u [NU + 1];
__device__ int g_cnt_i[NI];
__device__ int g_cnt_u[NU];
__device__ int g_col_i[NE];
__device__ int g_col_u[NE];
__device__ int g_bsum_i[32];
__device__ int g_bsum_u[32];

// ---------------- tf32 helpers -------------------------------------------------
__device__ __forceinline__ uint32_t f2tf32(float x) {
    uint32_t u;
    asm("cvt.rna.tf32.f32 %0, %1;" : "=r"(u) : "f"(x));
    return u;
}
__device__ __forceinline__ float rndtf32(float x) {
    return __uint_as_float(f2tf32(x));
}

#define WO_PU 0
#define WO_PI 8192
#define WO_WL 24576
#define WO_WR 90112
#define W_TOT 155648
__global__ void round_w(const float* __restrict__ pu, const float* __restrict__ pi,
                        const float* __restrict__ wl, const float* __restrict__ wr,
                        float* __restrict__ o) {
    int i = blockIdx.x * blockDim.x + threadIdx.x;
    float v;
    if (i < WO_PI) v = pu[i];
    else if (i < WO_WL) v = pi[i - WO_PI];
    else if (i < WO_WR) v = wl[i - WO_WL];
    else if (i < W_TOT) v = wr[i - WO_WR];
    else return;
    o[i] = rndtf32(v);
}

// ---------------- layer-0 weight composition -----------------------------------
#define WC_U0 0
#define WC_U1 8192
#define WC_I0 16384
#define WC_I1 32768
#define WC_B  49152
__global__ __launch_bounds__(128) void compose_w(
    const float* __restrict__ Wp_u, const float* __restrict__ bp_u,
    const float* __restrict__ Wp_i, const float* __restrict__ bp_i,
    const float* __restrict__ Wl, const float* __restrict__ bl,
    const float* __restrict__ Wr, const float* __restrict__ br,
    float* __restrict__ wc)
{
    const size_t HH = (size_t)H * H;
    const float* Wp; const float* bp; const float* Ws; const float* bs;
    float* Wo; float* bo; int inDim;
    switch (blockIdx.y) {
        case 0:  Wp = Wp_u; bp = bp_u; Ws = Wl;      bs = bl;     Wo = wc + WC_U0; bo = wc + WC_B;       inDim = 64;  break; // xlu
        case 1:  Wp = Wp_u; bp = bp_u; Ws = Wr + HH; bs = br + H; Wo = wc + WC_U1; bo = wc + WC_B + 128; inDim = 64;  break; // xru
        case 2:  Wp = Wp_i; bp = bp_i; Ws = Wr;      bs = br;     Wo = wc + WC_I0; bo = wc + WC_B + 256; inDim = 128; break; // xri
        default: Wp = Wp_i; bp = bp_i; Ws = Wl + HH; bs = bl + H; Wo = wc + WC_I1; bo = wc + WC_B + 384; inDim = 128; break; // xli
    }
    int i = blockIdx.x;
    int j = threadIdx.x;
    if (i < inDim) {
        float s = 0.f;
#pragma unroll 8
        for (int k = 0; k < 128; k++)
            s += Wp[i * 128 + k] * Ws[k * 128 + j];
        Wo[i * 128 + j] = rndtf32(s);
    } else if (i == inDim) {
        float s = bs[j];
#pragma unroll 8
        for (int k = 0; k < 128; k++)
            s += bp[k] * Ws[k * 128 + j];
        bo[j] = s;
    }
}

// ---------------- tf32 tensor-core GEMM, cp.async 2-stage pipeline -------------
#define BM 128
#define BN 128
#define BK 32
#define AST 36
#define BST 136
#define SMEM_BYTES ((2*BM*AST + 2*BK*BST) * 4)

template<int N> struct IC { static constexpr int v = N; };

__device__ __forceinline__ void cp16(uint32_t dst, const float* src, bool pred) {
    asm volatile("cp.async.ca.shared.global [%0], [%1], 16, %2;"
                 :: "r"(dst), "l"(src), "r"(pred ? 16 : 0));
}

template<int KTU, int KTI>
__global__ __launch_bounds__(256, 2) void gemm_fused(
    const float* __restrict__ Au, int Mu, int Ku,
    const float* __restrict__ Ai, int Mi, int Ki, int UB,
    const float* __restrict__ W00, const float* __restrict__ b00, float* __restrict__ C00,
    const float* __restrict__ W01, const float* __restrict__ b01, float* __restrict__ C01,
    const float* __restrict__ W10, const float* __restrict__ b10, float* __restrict__ C10,
    const float* __restrict__ W11, const float* __restrict__ b11, float* __restrict__ C11,
    int cvtA, int roundC)
{
    extern __shared__ float smbuf[];
    const int sec = (blockIdx.y >= (unsigned)UB) ? 1 : 0;
    const float* A = sec ? Ai : Au;
    const int M = sec ? Mi : Mu;
    const int K = sec ? Ki : Ku;
    const int bm = (sec ? (blockIdx.y - UB) : blockIdx.y) * BM;

    const float* W; const float* bv; float* C;
    if (!sec) { if (blockIdx.x == 0) { W=W00; bv=b00; C=C00; } else { W=W01; bv=b01; C=C01; } }
    else      { if (blockIdx.x == 0) { W=W10; bv=b10; C=C10; } else { W=W11; bv=b11; C=C11; } }

    const int tid  = threadIdx.x;
    const int lane = tid & 31;
    const int warp = tid >> 5;
    const int wm   = warp >> 2;
    const int wn   = warp & 3;

    float* As = smbuf;
    float* Bs = smbuf + 2 * BM * AST;

    const int arow = tid >> 3;
    const int acol = (tid & 7) * 4;
    const int brow = tid >> 5;
    const int bcol = (tid & 31) * 4;

    float acc[4][4][4];
#pragma unroll
    for (int mt = 0; mt < 4; mt++)
#pragma unroll
        for (int nt = 0; nt < 4; nt++)
#pragma unroll
            for (int c = 0; c < 4; c++) acc[mt][nt][c] = 0.f;

    auto stage = [&](int kt, int buf) {
#pragma unroll
        for (int i = 0; i < 4; i++) {
            int row = arow + 32 * i;
            bool p = (bm + row) < M;
            int r = p ? (bm + row) : (M - 1);
            uint32_t d = (uint32_t)__cvta_generic_to_shared(As + buf * BM * AST + row * AST + acol);
            cp16(d, A + (size_t)r * K + kt * BK + acol, p);
        }
#pragma unroll
        for (int i = 0; i < 4; i++) {
            int kr = brow + 8 * i;
            uint32_t d = (uint32_t)__cvta_generic_to_shared(Bs + buf * BK * BST + kr * BST + bcol);
            cp16(d, W + (size_t)(kt * BK + kr) * BN + bcol, true);
        }
    };

    auto compute = [&](int buf) {
        const float* Asb = As + buf * BM * AST;
        const float* Bsb = Bs + buf * BK * BST;
#pragma unroll
        for (int kk = 0; kk < 4; kk++) {
            uint32_t a[4][4];
            {
                int row  = wm * 64 + (lane & 15);
                int koff = kk * 8 + ((lane >> 4) << 2);
#pragma unroll
                for (int mt = 0; mt < 4; mt++) {
                    uint32_t sa = (uint32_t)__cvta_generic_to_shared(
                        Asb + (row + mt * 16) * AST + koff);
                    asm volatile(
                        "ldmatrix.sync.aligned.m8n8.x4.shared.b16 {%0,%1,%2,%3}, [%4];"
                        : "=r"(a[mt][0]), "=r"(a[mt][1]), "=r"(a[mt][2]), "=r"(a[mt][3])
                        : "r"(sa));
                }
            }
            if (cvtA) {
#pragma unroll
                for (int mt = 0; mt < 4; mt++)
#pragma unroll
                    for (int i = 0; i < 4; i++)
                        a[mt][i] = f2tf32(__uint_as_float(a[mt][i]));
            }

            uint32_t b[4][2];
            {
                int kb = kk * 8 + (lane & 3);
                int nb = wn * 32 + (lane >> 2);
#pragma unroll
                for (int nt = 0; nt < 4; nt++) {
                    b[nt][0] = __float_as_uint(Bsb[kb * BST + nb + nt * 8]);
                    b[nt][1] = __float_as_uint(Bsb[(kb + 4) * BST + nb + nt * 8]);
                }
            }
#pragma unroll
            for (int mt = 0; mt < 4; mt++)
#pragma unroll
                for (int nt = 0; nt < 4; nt++) {
                    asm volatile(
                        "mma.sync.aligned.m16n8k8.row.col.f32.tf32.tf32.f32 "
                        "{%0,%1,%2,%3}, {%4,%5,%6,%7}, {%8,%9}, {%0,%1,%2,%3};"
                        : "+f"(acc[mt][nt][0]), "+f"(acc[mt][nt][1]),
                          "+f"(acc[mt][nt][2]), "+f"(acc[mt][nt][3])
                        : "r"(a[mt][0]), "r"(a[mt][1]), "r"(a[mt][2]), "r"(a[mt][3]),
                          "r"(b[nt][0]), "r"(b[nt][1]));
                }
        }
    };

    auto run = [&](auto ktc) {
        constexpr int KT = decltype(ktc)::v;
        stage(0, 0);
        asm volatile("cp.async.commit_group;");
#pragma unroll
        for (int kt = 0; kt < KT; kt++) {
            int buf = kt & 1;
            if (kt + 1 < KT) {
                stage(kt + 1, buf ^ 1);
                asm volatile("cp.async.commit_group;");
                asm volatile("cp.async.wait_group 1;");
            } else {
                asm volatile("cp.async.wait_group 0;");
            }
            __syncthreads();
            compute(buf);
            if (kt + 1 < KT) __syncthreads();   // final barrier unnecessary:
                                                // epilogue touches no smem
        }
    };
    if (sec == 0) run(IC<KTU>{});
    else          run(IC<KTI>{});

    // epilogue: bias values hoisted (8 distinct loads instead of 32)
    const int r0 = bm + wm * 64 + (lane >> 2);
    const int cb = wn * 32 + 2 * (lane & 3);
    float bvx[4], bvy[4];
#pragma unroll
    for (int nt = 0; nt < 4; nt++) {
        int col = cb + nt * 8;
        bvx[nt] = bv[col];
        bvy[nt] = bv[col + 1];
    }
#pragma unroll
    for (int mt = 0; mt < 4; mt++) {
#pragma unroll
        for (int nt = 0; nt < 4; nt++) {
            int row = r0 + mt * 16;
            int col = cb + nt * 8;
            if (row < M) {
                float2 v = make_float2(acc[mt][nt][0] + bvx[nt], acc[mt][nt][1] + bvy[nt]);
                if (roundC) { v.x = rndtf32(v.x); v.y = rndtf32(v.y); }
                *(float2*)(C + (size_t)row * BN + col) = v;
            }
            if (row + 8 < M) {
                float2 v = make_float2(acc[mt][nt][2] + bvx[nt], acc[mt][nt][3] + bvy[nt]);
                if (roundC) { v.x = rndtf32(v.x); v.y = rndtf32(v.y); }
                *(float2*)(C + (size_t)(row + 8) * BN + col) = v;
            }
        }
    }
}

// ---------------- CSR construction (once per call) -----------------------------
__global__ void zero_counts(int* __restrict__ ci, int* __restrict__ cu) {
    int i = blockIdx.x * blockDim.x + threadIdx.x;
    if (i < NI) ci[i] = 0;
    if (i < NU) cu[i] = 0;
}

__global__ void build_hist(const int* __restrict__ es, const int* __restrict__ ed,
                           int* __restrict__ cu, int* __restrict__ ci, int nE) {
    int i = blockIdx.x * blockDim.x + threadIdx.x;
    if (i < nE) {
        atomicAdd(ci + ed[i], 1);
        atomicAdd(cu + es[i], 1);
    }
}

__global__ __launch_bounds__(1024) void scan_p1_both(
    const int* __restrict__ ci, int* __restrict__ bi, int nbi, int ni,
    const int* __restrict__ cu, int* __restrict__ bu, int nu)
{
    __shared__ int sh[1024];
    const int* cnt; int* bsums; int n; int blk;
    if ((int)blockIdx.x < nbi) { cnt = ci; bsums = bi; n = ni; blk = blockIdx.x; }
    else { cnt = cu; bsums = bu; n = nu; blk = blockIdx.x - nbi; }
    int base = blk * 4096;
    int t = threadIdx.x;
    int s = 0;
#pragma unroll
    for (int j = 0; j < 4; j++) {
        int i = base + t * 4 + j;
        if (i < n) s += cnt[i];
    }
    sh[t] = s;
    __syncthreads();
    for (int d = 512; d > 0; d >>= 1) {
        if (t < d) sh[t] += sh[t + d];
        __syncthreads();
    }
    if (t == 0) bsums[blk] = sh[0];
}

__global__ void scan_p2_both(int* __restrict__ bi, int nbi, int* __restrict__ rpi, int ni,
                             int* __restrict__ bu, int nbu, int* __restrict__ rpu, int nu) {
    int w = threadIdx.x >> 5;
    int t = threadIdx.x & 31;
    int* bs = w ? bu : bi;
    int nb = w ? nbu : nbi;
    int* rp = w ? rpu : rpi;
    int n  = w ? nu : ni;
    int own = (t < nb) ? bs[t] : 0;
    int v = own;
#pragma unroll
    for (int d = 1; d < 32; d <<= 1) {
        int u = __shfl_up_sync(0xffffffffu, v, d);
        if (t >= d) v += u;
    }
    if (t < nb) bs[t] = v - own;
    if (t == nb - 1) rp[n] = v;
}

__global__ __launch_bounds__(1024) void scan_p3_both(
    const int* __restrict__ ci, const int* __restrict__ bi, int nbi,
    int* __restrict__ rpi, int* __restrict__ curi, int ni,
    const int* __restrict__ cu, const int* __restrict__ bu,
    int* __restrict__ rpu, int* __restrict__ curu, int nu)
{
    __shared__ int sh[1024];
    const int* cnt; const int* bsums; int* rp; int* cur; int n; int blk;
    if ((int)blockIdx.x < nbi) { cnt = ci; bsums = bi; rp = rpi; cur = curi; n = ni; blk = blockIdx.x; }
    else { cnt = cu; bsums = bu; rp = rpu; cur = curu; n = nu; blk = blockIdx.x - nbi; }
    int base = blk * 4096;
    int t = threadIdx.x;
    int c[4];
    int s = 0;
#pragma unroll
    for (int j = 0; j < 4; j++) {
        int i = base + t * 4 + j;
        c[j] = (i < n) ? cnt[i] : 0;
        s += c[j];
    }
    sh[t] = s;
    __syncthreads();
    for (int d = 1; d < 1024; d <<= 1) {
        int v = (t >= d) ? sh[t - d] : 0;
        __syncthreads();
        sh[t] += v;
        __syncthreads();
    }
    int off = bsums[blk] + ((t > 0) ? sh[t - 1] : 0);
#pragma unroll
    for (int j = 0; j < 4; j++) {
        int i = base + t * 4 + j;
        if (i < n) {
            rp[i] = off;
            cur[i] = off;
            off += c[j];
        }
    }
}

__global__ void fill_csr(const int* __restrict__ es, const int* __restrict__ ed,
                         int* __restrict__ cur_u, int* __restrict__ cur_i,
                         int* __restrict__ col_u, int* __restrict__ col_i, int nE) {
    int i = blockIdx.x * blockDim.x + threadIdx.x;
    if (i < nE) {
        int s = es[i], t = ed[i];
        col_i[atomicAdd(cur_i + t, 1)] = s;
        col_u[atomicAdd(cur_u + s, 1)] = t;
    }
}

// ---------------- fused GATv2 gather (both relations of one layer) -------------
// R8/R13 loop form — locked. postOut=1: relu + tf32-round at write.
__global__ __launch_bounds__(256) void gat_gather(
    const float* __restrict__ xlu, const float* __restrict__ xri,
    const float* __restrict__ att0, const float* __restrict__ bias0,
    float* __restrict__ outI,
    const float* __restrict__ xli, const float* __restrict__ xru,
    const float* __restrict__ att1, const float* __restrict__ bias1,
    float* __restrict__ outU,
    const int* __restrict__ rp_i, const int* __restrict__ col_i,
    const int* __restrict__ rp_u, const int* __restrict__ col_u,
    int postOut)
{
    int w = (blockIdx.x * blockDim.x + threadIdx.x) >> 5;
    int lane = threadIdx.x & 31;

    const float* xl; const float* xr; const float* att; const float* bias;
    float* out; const int* rp; const int* col; int t;
    if (w < NI) {
        t = w; xl = xlu; xr = xri; att = att0; bias = bias0; out = outI;
        rp = rp_i; col = col_i;
    } else if (w < NI + NU) {
        t = w - NI; xl = xli; xr = xru; att = att1; bias = bias1; out = outU;
        rp = rp_u; col = col_u;
    } else return;

    int beg = rp[t], end = rp[t + 1];
    float4 b4 = *(const float4*)(bias + lane * 4);
    float* o = out + (size_t)t * H + lane * 4;

    if (beg == end) {
        if (postOut) {
            b4.x = rndtf32(fmaxf(b4.x, 0.f)); b4.y = rndtf32(fmaxf(b4.y, 0.f));
            b4.z = rndtf32(fmaxf(b4.z, 0.f)); b4.w = rndtf32(fmaxf(b4.w, 0.f));
        }
        *(float4*)o = b4;
        return;
    }

    float4 xr4 = *(const float4*)(xr + (size_t)t * H + lane * 4);
    float4 at4 = *(const float4*)(att + lane * 4);

    float a0 = 0.f, a1 = 0.f, a2 = 0.f, a3 = 0.f, den = 0.f;

    int e = beg;
    for (; e + 2 <= end; e += 2) {
        int s0 = col[e], s1 = col[e + 1];
        float4 xA = *(const float4*)(xl + (size_t)s0 * H + lane * 4);
        float4 xB = *(const float4*)(xl + (size_t)s1 * H + lane * 4);

        float eA0 = xA.x + xr4.x; eA0 = (eA0 > 0.f) ? eA0 : 0.2f * eA0;
        float eA1 = xA.y + xr4.y; eA1 = (eA1 > 0.f) ? eA1 : 0.2f * eA1;
        float eA2 = xA.z + xr4.z; eA2 = (eA2 > 0.f) ? eA2 : 0.2f * eA2;
        float eA3 = xA.w + xr4.w; eA3 = (eA3 > 0.f) ? eA3 : 0.2f * eA3;
        float pA = eA0 * at4.x + eA1 * at4.y + eA2 * at4.z + eA3 * at4.w;

        float eB0 = xB.x + xr4.x; eB0 = (eB0 > 0.f) ? eB0 : 0.2f * eB0;
        float eB1 = xB.y + xr4.y; eB1 = (eB1 > 0.f) ? eB1 : 0.2f * eB1;
        float eB2 = xB.z + xr4.z; eB2 = (eB2 > 0.f) ? eB2 : 0.2f * eB2;
        float eB3 = xB.w + xr4.w; eB3 = (eB3 > 0.f) ? eB3 : 0.2f * eB3;
        float pB = eB0 * at4.x + eB1 * at4.y + eB2 * at4.z + eB3 * at4.w;

#pragma unroll
        for (int off = 8; off > 0; off >>= 1) {
            pA += __shfl_xor_sync(0xffffffffu, pA, off);
            pB += __shfl_xor_sync(0xffffffffu, pB, off);
        }
        float peA = expf(pA);
        float peB = expf(pB);
        den += peA + peB;
        a0 += peA * xA.x + peB * xB.x;
        a1 += peA * xA.y + peB * xB.y;
        a2 += peA * xA.z + peB * xB.z;
        a3 += peA * xA.w + peB * xB.w;
    }
    if (e < end) {
        int s0 = col[e];
        float4 xA = *(const float4*)(xl + (size_t)s0 * H + lane * 4);
        float eA0 = xA.x + xr4.x; eA0 = (eA0 > 0.f) ? eA0 : 0.2f * eA0;
        float eA1 = xA.y + xr4.y; eA1 = (eA1 > 0.f) ? eA1 : 0.2f * eA1;
        float eA2 = xA.z + xr4.z; eA2 = (eA2 > 0.f) ? eA2 : 0.2f * eA2;
        float eA3 = xA.w + xr4.w; eA3 = (eA3 > 0.f) ? eA3 : 0.2f * eA3;
        float pA = eA0 * at4.x + eA1 * at4.y + eA2 * at4.z + eA3 * at4.w;
#pragma unroll
        for (int off = 8; off > 0; off >>= 1)
            pA += __shfl_xor_sync(0xffffffffu, pA, off);
        float peA = expf(pA);
        den += peA;
        a0 += peA * xA.x;
        a1 += peA * xA.y;
        a2 += peA * xA.z;
        a3 += peA * xA.w;
    }

    float inv = 1.f / (den + 1e-16f);
    float4 r;
    r.x = a0 * inv + b4.x;
    r.y = a1 * inv + b4.y;
    r.z = a2 * inv + b4.z;
    r.w = a3 * inv + b4.w;
    if (postOut) {
        r.x = rndtf32(fmaxf(r.x, 0.f)); r.y = rndtf32(fmaxf(r.y, 0.f));
        r.z = rndtf32(fmaxf(r.z, 0.f)); r.w = rndtf32(fmaxf(r.w, 0.f));
    }
    *(float4*)o = r;
}

extern "C" void kernel_launch(void* const* d_in, const int* in_sizes, int n_in,
                              void* d_out, int out_size)
{
    const float* x_user  = (const float*)d_in[0];
    const float* x_item  = (const float*)d_in[1];
    const float* Wp_user = (const float*)d_in[2];
    const float* bp_user = (const float*)d_in[3];
    const float* Wp_item = (const float*)d_in[4];
    const float* bp_item = (const float*)d_in[5];
    const float* Wl      = (const float*)d_in[6];
    const float* bl      = (const float*)d_in[7];
    const float* Wr      = (const float*)d_in[8];
    const float* br      = (const float*)d_in[9];
    const float* att     = (const float*)d_in[10];
    const float* bias    = (const float*)d_in[11];
    const int*   e_src   = (const int*)d_in[12];
    const int*   e_dst   = (const int*)d_in[13];
    const int    nE      = in_sizes[12];

    float* out = (float*)d_out;

    float *zu2, *zi2, *xlu, *xru, *xli, *xri, *wtf, *wc;
    int *rp_i, *rp_u, *cnt_i, *cnt_u, *col_i, *col_u, *bs_i, *bs_u;
    cudaGetSymbolAddress((void**)&zu2, g_zu2);
    cudaGetSymbolAddress((void**)&zi2, g_zi2);
    cudaGetSymbolAddress((void**)&xlu, g_xlu);
    cudaGetSymbolAddress((void**)&xru, g_xru);
    cudaGetSymbolAddress((void**)&xli, g_xli);
    cudaGetSymbolAddress((void**)&xri, g_xri);
    cudaGetSymbolAddress((void**)&wtf, g_wtf);
    cudaGetSymbolAddress((void**)&wc,  g_wc);
    cudaGetSymbolAddress((void**)&rp_i,  g_rp_i);
    cudaGetSymbolAddress((void**)&rp_u,  g_rp_u);
    cudaGetSymbolAddress((void**)&cnt_i, g_cnt_i);
    cudaGetSymbolAddress((void**)&cnt_u, g_cnt_u);
    cudaGetSymbolAddress((void**)&col_i, g_col_i);
    cudaGetSymbolAddress((void**)&col_u, g_col_u);
    cudaGetSymbolAddress((void**)&bs_i,  g_bsum_i);
    cudaGetSymbolAddress((void**)&bs_u,  g_bsum_u);

    cudaFuncSetAttribute(gemm_fused<2,4>, cudaFuncAttributeMaxDynamicSharedMemorySize, SMEM_BYTES);
    cudaFuncSetAttribute(gemm_fused<4,4>, cudaFuncAttributeMaxDynamicSharedMemorySize, SMEM_BYTES);

    // side stream + events (created once, before graph capture begins)
    static cudaStream_t s2 = nullptr;
    static cudaEvent_t evFork = nullptr, evJoin = nullptr;
    if (s2 == nullptr) {
        cudaStreamCreateWithFlags(&s2, cudaStreamNonBlocking);
        cudaEventCreateWithFlags(&evFork, cudaEventDisableTiming);
        cudaEventCreateWithFlags(&evJoin, cudaEventDisableTiming);
    }

    cudaStream_t st = 0;
    const int UB = (NU + BM - 1) / BM;
    const int IB = (NI + BM - 1) / BM;
    const int NB_I = (NI + 4095) / 4096;
    const int NB_U = (NU + 4095) / 4096;

    // ---- fork: CSR build + layer-1 weight rounding on side stream ----
    cudaEventRecord(evFork, st);
    cudaStreamWaitEvent(s2, evFork, 0);

    zero_counts<<<(NU + 255) / 256, 256, 0, s2>>>(cnt_i, cnt_u);
    build_hist<<<(nE + 255) / 256, 256, 0, s2>>>(e_src, e_dst, cnt_u, cnt_i, nE);
    scan_p1_both<<<NB_I + NB_U, 1024, 0, s2>>>(cnt_i, bs_i, NB_I, NI, cnt_u, bs_u, NU);
    scan_p2_both<<<1, 64, 0, s2>>>(bs_i, NB_I, rp_i, NI, bs_u, NB_U, rp_u, NU);
    scan_p3_both<<<NB_I + NB_U, 1024, 0, s2>>>(cnt_i, bs_i, NB_I, rp_i, cnt_i, NI,
                                               cnt_u, bs_u, rp_u, cnt_u, NU);
    fill_csr<<<(nE + 255) / 256, 256, 0, s2>>>(e_src, e_dst, cnt_u, cnt_i, col_u, col_i, nE);
    round_w<<<(W_TOT + 255) / 256, 256, 0, s2>>>(Wp_user, Wp_item, Wl, Wr, wtf);
    cudaEventRecord(evJoin, s2);

    // ---- main stream: layer-0 weight composition (critical-path head) ----
    {
        dim3 grid(129, 4);
        compose_w<<<grid, 128, 0, st>>>(Wp_user, bp_user, Wp_item, bp_item,
                                        Wl, bl, Wr, br, wc);
    }

    const int GBLK = ((NI + NU) * 32 + 255) / 256;
    bool joined = false;

    for (int l = 0; l < 2; l++) {
        int r0 = l * 2 + 0;
        int r1 = l * 2 + 1;
        float* outU = (l == 0) ? zu2 : out;
        float* outI = (l == 0) ? zi2 : out + (size_t)NU * H;

        if (l == 0) {
            // fused projection+layer0: A = raw inputs, W = composed weights
            dim3 grid(2, UB + IB);
            gemm_fused<2,4><<<grid, 256, SMEM_BYTES, st>>>(
                x_user, NU, 64, x_item, NI, 128, UB,
                wc + WC_U0, wc + WC_B,       xlu,
                wc + WC_U1, wc + WC_B + 128, xru,
                wc + WC_I0, wc + WC_B + 256, xri,
                wc + WC_I1, wc + WC_B + 384, xli,
                1, 0);
        } else {
            // layer 1: A (zu2/zi2) already relu'd + tf32-rounded by gather-0
            dim3 grid(2, UB + IB);
            gemm_fused<4,4><<<grid, 256, SMEM_BYTES, st>>>(
                zu2, NU, H, zi2, NI, H, UB,
                wtf + WO_WL + (size_t)r0 * 16384, bl + (size_t)r0 * H, xlu,
                wtf + WO_WR + (size_t)r1 * 16384, br + (size_t)r1 * H, xru,
                wtf + WO_WR + (size_t)r0 * 16384, br + (size_t)r0 * H, xri,
                wtf + WO_WL + (size_t)r1 * 16384, bl + (size_t)r1 * H, xli,
                0, 0);
        }

        if (!joined) {   // CSR (and wtf) must be ready before the first gather
            cudaStreamWaitEvent(st, evJoin, 0);
            joined = true;
        }

        gat_gather<<<GBLK, 256, 0, st>>>(
            xlu, xri, att + (size_t)r0 * H, bias + (size_t)r0 * H, outI,
            xli, xru, att + (size_t)r1 * H, bias + (size_t)r1 * H, outU,
            rp_i, col_i, rp_u, col_u,
            (l == 0) ? 1 : 0);
    }
}